// round 12
// baseline (speedup 1.0000x reference)
#include <cuda_runtime.h>
#include <cuda_fp16.h>
#include <cuda_fp8.h>
#include <math.h>
#include <stdint.h>

#define BATCH   16384
#define HID     1024
#define CTXK    512
#define N4      4096
#define TSTEPS  60
#define INW     516     // W_ih row width (C+4)

// gates GEMM, mixed precision:
//   fp16 section: A row = [h_hi(1024) | eblk(64)] -> AGLD=1088 = 17 tiles of k64
//     eblk = [e_hi(4) | e_lo(4) | zeros(56)]
//   fp8 section:  h_lo*2^7 (e4m3, 1024) x W/2^7 (e5m2) -> 8 tiles of k128
#define AGLD    1088
#define EBLK    1024
#define KG16    1088
#define NKG     25          // 17 fp16 + 8 fp8 tiles
#define KSG     17
// ffn GEMM (single fp16): A row = [y(1024)]
#define AFLD    1024
#define KF      1024
// context GEMMs (one-time, 3-term fp16): A row = [c_hi(512)|c_lo(512)];
//   K = [c_hi | c_lo | c_hi(re-read)] = 1536 ; W = [W_hi|W_hi|W_lo]
#define ACLD    1024
#define KC      1536

#define FP8SCALE    128.0f
#define FP8INV      0.0078125f

// ------------------------- scratch (device globals) -------------------------
__device__ __align__(256) float   g_gctx[(size_t)BATCH * N4];
__device__ __align__(256) __half  g_Ag0[(size_t)BATCH * AGLD];
__device__ __align__(256) __half  g_Ag1[(size_t)BATCH * AGLD];
__device__ __align__(256) uint8_t g_Al0[(size_t)BATCH * HID];     // h_lo e4m3*128
__device__ __align__(256) uint8_t g_Al1[(size_t)BATCH * HID];
__device__ __align__(256) __half  g_Af [(size_t)BATCH * AFLD];
__device__ __align__(256) __half  g_ctxs[(size_t)BATCH * ACLD];
__device__ __align__(256) float   g_c  [(size_t)BATCH * HID];
__device__ __align__(256) float   g_y2 [(size_t)BATCH * HID];
__device__ __align__(256) float   g_pos[(size_t)BATCH * 2];
__device__ __align__(256) __half  g_Wg  [(size_t)N4 * KG16];
__device__ __align__(256) uint8_t g_Wq  [(size_t)N4 * HID];       // Whh/128 e5m2
__device__ __align__(256) __half  g_Wc4 [(size_t)N4 * KC];
__device__ __align__(256) __half  g_Whh [(size_t)HID * KC];
__device__ __align__(256) __half  g_Wcc [(size_t)HID * KC];
__device__ __align__(256) __half  g_W1s [(size_t)HID * KF];
__device__ __align__(256) float   g_bsum[N4];

// ------------------------- low-level helpers -------------------------
#define SW128(b) ((b) ^ (((b) >> 3) & 0x70))

__device__ __forceinline__ void cpasync16(uint32_t dst, const void* src) {
    asm volatile("cp.async.cg.shared.global [%0],[%1],16;\n" :: "r"(dst), "l"(src));
}
__device__ __forceinline__ void ldsm4(uint32_t* r, uint32_t addr) {
    asm volatile("ldmatrix.sync.aligned.m8n8.x4.shared.b16 {%0,%1,%2,%3}, [%4];"
                 : "=r"(r[0]), "=r"(r[1]), "=r"(r[2]), "=r"(r[3]) : "r"(addr));
}
__device__ __forceinline__ void mma16816(float* c, const uint32_t* a, const uint32_t* b) {
    asm volatile(
        "mma.sync.aligned.m16n8k16.row.col.f32.f16.f16.f32 "
        "{%0,%1,%2,%3},{%4,%5,%6,%7},{%8,%9},{%0,%1,%2,%3};\n"
        : "+f"(c[0]), "+f"(c[1]), "+f"(c[2]), "+f"(c[3])
        : "r"(a[0]), "r"(a[1]), "r"(a[2]), "r"(a[3]), "r"(b[0]), "r"(b[1]));
}
// fp8 correction mma: identical fragment byte-layout to the fp16 k16 mma
__device__ __forceinline__ void mmafp8(float* c, const uint32_t* a, const uint32_t* b) {
    asm volatile(
        "mma.sync.aligned.m16n8k32.row.col.f32.e4m3.e5m2.f32 "
        "{%0,%1,%2,%3},{%4,%5,%6,%7},{%8,%9},{%0,%1,%2,%3};\n"
        : "+f"(c[0]), "+f"(c[1]), "+f"(c[2]), "+f"(c[3])
        : "r"(a[0]), "r"(a[1]), "r"(a[2]), "r"(a[3]), "r"(b[0]), "r"(b[1]));
}
__device__ __forceinline__ __half hhi(float v) { return __float2half_rn(v); }
__device__ __forceinline__ __half hlo(float v) {
    return __float2half_rn(v - __half2float(__float2half_rn(v)));
}
__device__ __forceinline__ uint8_t to_e4m3(float v) {
    return (uint8_t)__nv_cvt_float_to_fp8(v, __NV_SATFINITE, __NV_E4M3);
}
__device__ __forceinline__ uint8_t to_e5m2(float v) {
    return (uint8_t)__nv_cvt_float_to_fp8(v, __NV_SATFINITE, __NV_E5M2);
}
__device__ __forceinline__ float from_e4m3(uint8_t b) {
    __half_raw hr = __nv_cvt_fp8_to_halfraw(b, __NV_E4M3);
    return __half2float(*(__half*)&hr);
}
// fast activations: __expf (MUFU.EX2) + __fdividef (MUFU.RCP), rel err ~2^-21
__device__ __forceinline__ float fsig(float x) {
    return __fdividef(1.f, 1.f + __expf(-x));
}
__device__ __forceinline__ float ftanh(float x) {
    return 1.f - __fdividef(2.f, __expf(2.f * x) + 1.f);
}

// ------------------------- prep kernels -------------------------
__global__ void prep_weights(const float* __restrict__ Whh, const float* __restrict__ Wih,
                             const float* __restrict__ b_ih, const float* __restrict__ b_hh,
                             const float* __restrict__ Wh, const float* __restrict__ Wc,
                             const float* __restrict__ W1) {
    const long n_wg = (long)N4 * KG16;
    const long n_wq = (long)N4 * HID;
    const long n_wc = (long)N4 * KC;
    const long n_s  = (long)HID * CTXK;
    const long n_w1 = (long)HID * HID;
    long i = (long)blockIdx.x * blockDim.x + threadIdx.x;

    if (i < n_wg) {   // fp16: [Whh_hi(1024) | We(4)|We(4)|0...]
        int np = (int)(i / KG16), k = (int)(i % KG16);
        int r = (np & 3) * HID + (np >> 2);
        float w = 0.f;
        if (k < 1024)        w = Whh[(size_t)r * HID + k];
        else {
            int q = k - 1024;
            if (q < 4)        w = Wih[(size_t)r * INW + CTXK + q];
            else if (q < 8)   w = Wih[(size_t)r * INW + CTXK + (q - 4)];
        }
        g_Wg[(size_t)np * KG16 + k] = hhi(w);
        return;
    }
    i -= n_wg;
    if (i < n_wq) {   // e5m2: Whh / 128
        int np = (int)(i / HID), k = (int)(i % HID);
        int r = (np & 3) * HID + (np >> 2);
        g_Wq[(size_t)np * HID + k] = to_e5m2(Whh[(size_t)r * HID + k] * FP8INV);
        return;
    }
    i -= n_wq;
    if (i < n_wc) {   // W_ih ctx part (3-term): [hi(512)|hi(512)|lo(512)]
        int np = (int)(i / KC), k = (int)(i % KC);
        int r = (np & 3) * HID + (np >> 2);
        int src = (k < 512) ? k : (k < 1024 ? k - 512 : k - 1024);
        float w = Wih[(size_t)r * INW + src];
        g_Wc4[(size_t)np * KC + k] = (k < 1024) ? hhi(w) : hlo(w);
        return;
    }
    i -= n_wc;
    if (i < N4) {
        int r = ((int)i & 3) * HID + ((int)i >> 2);
        g_bsum[i] = b_ih[r] + b_hh[r];
        return;
    }
    i -= N4;
    if (i < n_s) {    // Wh (3-term): [hi|hi|lo]
        int r = (int)(i / CTXK), k = (int)(i % CTXK);
        float w = Wh[(size_t)r * CTXK + k];
        size_t b = (size_t)r * KC;
        g_Whh[b + k] = hhi(w); g_Whh[b + 512 + k] = hhi(w); g_Whh[b + 1024 + k] = hlo(w);
        return;
    }
    i -= n_s;
    if (i < n_s) {    // Wc (3-term)
        int r = (int)(i / CTXK), k = (int)(i % CTXK);
        float w = Wc[(size_t)r * CTXK + k];
        size_t b = (size_t)r * KC;
        g_Wcc[b + k] = hhi(w); g_Wcc[b + 512 + k] = hhi(w); g_Wcc[b + 1024 + k] = hlo(w);
        return;
    }
    i -= n_s;
    if (i < n_w1) {   // W1 (single fp16)
        int r = (int)(i / HID), k = (int)(i % HID);
        g_W1s[(size_t)r * KF + k] = hhi(W1[(size_t)r * HID + k]);
    }
}

__global__ void prep_data(const float* __restrict__ ctx,
                          const float* __restrict__ last_pos,
                          const float* __restrict__ last_delta) {
    const long n_cs = (long)BATCH * CTXK;
    long i = (long)blockIdx.x * blockDim.x + threadIdx.x;
    if (i < n_cs) {
        int b = (int)(i / CTXK), k = (int)(i % CTXK);
        float v = ctx[i];
        g_ctxs[(size_t)b * ACLD + k]       = hhi(v);
        g_ctxs[(size_t)b * ACLD + 512 + k] = hlo(v);
        return;
    }
    i -= n_cs;
    if (i < BATCH) {
        int b = (int)i;
        g_pos[b * 2 + 0] = last_pos[b * 2 + 0];
        g_pos[b * 2 + 1] = last_pos[b * 2 + 1];
        float d0 = last_delta[b * 2 + 0], d1 = last_delta[b * 2 + 1];
        float nn = fmaxf(sqrtf(d0 * d0 + d1 * d1), 1e-6f);
        float e[4] = {d0, d1, d0 / nn, d1 / nn};
        size_t base = (size_t)b * AGLD;
#pragma unroll
        for (int q = 0; q < 4; q++) {
            g_Ag0[base + EBLK + q]     = hhi(e[q]);
            g_Ag0[base + EBLK + 4 + q] = hlo(e[q]);
        }
        __half z = __float2half(0.f);
        for (int k = EBLK + 8; k < AGLD; k++) { g_Ag0[base + k] = z; g_Ag1[base + k] = z; }
    }
}

// ------------------------- GEMM engine (mixed fp16 + fp8 K-tiles) ----------
// 128x128 CTA tile, 3-slot smem ring / 2 tiles in flight, ldmatrix,
// one __syncthreads per K-tile. fp16 tile = k64 (128B rows); fp8 tile = k128
// (128B rows) — identical smem layout & fragment loads; only the mma differs.
#define NSTG 3
#define STG_BYTES 32768          // A 16KB + B 16KB
#define GEMM_SMEM (NSTG * STG_BYTES)

enum { EPI_CTX = 0, EPI_TANH_SPLIT = 1, EPI_TANH_C = 2, EPI_GATES = 3, EPI_GELU = 4 };

__device__ __forceinline__ void lstm_cell(float* cbuf, __half* outs, uint8_t* outs8,
                                          int row, int j,
                                          float gi, float gf, float gg, float go) {
    float cold = cbuf[(size_t)row * HID + j];
    float si = fsig(gi);
    float sf = fsig(gf);
    float so = fsig(go);
    float tg = ftanh(gg);
    float cn = sf * cold + si * tg;
    float h  = so * ftanh(cn);
    cbuf[(size_t)row * HID + j] = cn;
    __half hh = hhi(h);
    outs[(size_t)row * AGLD + j] = hh;
    outs8[(size_t)row * HID + j] = to_e4m3((h - __half2float(hh)) * FP8SCALE);
}

template <int EPI>
__global__ void __launch_bounds__(256, 2)
gemm2(const __half* __restrict__ Af, int ldaf,
      const uint8_t* __restrict__ A8,            // fp8 activations, row stride HID
      const __half* __restrict__ Wf, int ktf,    // fp16 weights row stride
      const uint8_t* __restrict__ W8,            // fp8 weights, row stride HID
      int nK, int kS,                            // total K-tiles, fp16 K-tiles
      int s1, int d1,                            // fp16 K->A col remap
      const float* __restrict__ aux,
      float* __restrict__ outf,
      __half* __restrict__ outs,
      uint8_t* __restrict__ outs8,
      int nOut) {
    extern __shared__ __align__(1024) char smp[];
    const uint32_t sbase = (uint32_t)__cvta_generic_to_shared(smp);

    const int tid = threadIdx.x;
    const int lane = tid & 31, wid = tid >> 5;
    const int wm = wid >> 2, wn = wid & 3;
    const int m0 = blockIdx.y * 128, n0 = blockIdx.x * 128;

    float acc[4][4][4];
#pragma unroll
    for (int a = 0; a < 4; a++)
#pragma unroll
        for (int b = 0; b < 4; b++)
#pragma unroll
            for (int c = 0; c < 4; c++) acc[a][b][c] = 0.f;

    auto fill = [&](int kt) {
        int slot = kt % NSTG;
        uint32_t sA = sbase + slot * STG_BYTES;
        uint32_t sB = sA + 16384;
        if (kt < kS) {
            int k0 = kt * 64;
            int cb = (k0 < s1) ? k0 : k0 - d1;
#pragma unroll
            for (int t = 0; t < 4; t++) {
                int c = tid + t * 256;
                int row = c >> 3, ch = c & 7;
                cpasync16(sA + SW128(row * 128 + ch * 16),
                          Af + (size_t)(m0 + row) * ldaf + cb + ch * 8);
            }
#pragma unroll
            for (int t = 0; t < 4; t++) {
                int c = tid + t * 256;
                int row = c >> 3, ch = c & 7;
                cpasync16(sB + SW128(row * 128 + ch * 16),
                          Wf + (size_t)(n0 + row) * ktf + k0 + ch * 8);
            }
        } else {
            int k0 = (kt - kS) * 128;                 // fp8 elements = bytes
#pragma unroll
            for (int t = 0; t < 4; t++) {
                int c = tid + t * 256;
                int row = c >> 3, ch = c & 7;
                cpasync16(sA + SW128(row * 128 + ch * 16),
                          A8 + (size_t)(m0 + row) * HID + k0 + ch * 16);
            }
#pragma unroll
            for (int t = 0; t < 4; t++) {
                int c = tid + t * 256;
                int row = c >> 3, ch = c & 7;
                cpasync16(sB + SW128(row * 128 + ch * 16),
                          W8 + (size_t)(n0 + row) * HID + k0 + ch * 16);
            }
        }
        asm volatile("cp.async.commit_group;\n");
    };

    // prologue: 2 tiles in flight
    fill(0);
    if (nK > 1) fill(1);

    const int g  = lane >> 3;
    const int lr = lane & 7;

    for (int kt = 0; kt < nK; kt++) {
        if (kt + 1 < nK) asm volatile("cp.async.wait_group 1;\n");
        else             asm volatile("cp.async.wait_group 0;\n");
        __syncthreads();                       // all warps done reading slot (kt-1)%3
        if (kt + 2 < nK) fill(kt + 2);         // safe: overwrites slot (kt-1)%3

        int slot = kt % NSTG;
        uint32_t sA = sbase + slot * STG_BYTES;
        uint32_t sB = sA + 16384;
        bool f8 = (kt >= kS);

#pragma unroll
        for (int ks = 0; ks < 4; ks++) {
            uint32_t a[4][4], b[2][4];
#pragma unroll
            for (int mf = 0; mf < 4; mf++) {
                int row = wm * 64 + mf * 16 + lr + ((g & 1) << 3);
                ldsm4(a[mf], sA + SW128(row * 128 + ks * 32 + ((g >> 1) << 4)));
            }
#pragma unroll
            for (int nf = 0; nf < 2; nf++) {
                int row = wn * 32 + nf * 16 + lr + ((g >> 1) << 3);
                ldsm4(b[nf], sB + SW128(row * 128 + ks * 32 + ((g & 1) << 4)));
            }
            if (!f8) {
#pragma unroll
                for (int mf = 0; mf < 4; mf++)
#pragma unroll
                    for (int nf = 0; nf < 2; nf++) {
                        mma16816(acc[mf][2 * nf],     a[mf], &b[nf][0]);
                        mma16816(acc[mf][2 * nf + 1], a[mf], &b[nf][2]);
                    }
            } else {
#pragma unroll
                for (int mf = 0; mf < 4; mf++)
#pragma unroll
                    for (int nf = 0; nf < 2; nf++) {
                        mmafp8(acc[mf][2 * nf],     a[mf], &b[nf][0]);
                        mmafp8(acc[mf][2 * nf + 1], a[mf], &b[nf][2]);
                    }
            }
        }
    }

    // ------------------------- epilogue -------------------------
#pragma unroll
    for (int mt = 0; mt < 4; mt++) {
#pragma unroll
        for (int nt = 0; nt < 4; nt++) {
            int r = m0 + wm * 64 + mt * 16 + (lane >> 2);
            int n = n0 + wn * 32 + nt * 8 + (lane & 3) * 2;
            float v0 = acc[mt][nt][0], v1 = acc[mt][nt][1];
            float v2 = acc[mt][nt][2], v3 = acc[mt][nt][3];

            if (EPI == EPI_CTX) {
                outf[(size_t)r * nOut + n]           = v0 + aux[n];
                outf[(size_t)r * nOut + n + 1]       = v1 + aux[n + 1];
                outf[(size_t)(r + 8) * nOut + n]     = v2 + aux[n];
                outf[(size_t)(r + 8) * nOut + n + 1] = v3 + aux[n + 1];
            } else if (EPI == EPI_TANH_C) {
                outf[(size_t)r * nOut + n]           = ftanh(v0 + aux[n]);
                outf[(size_t)r * nOut + n + 1]       = ftanh(v1 + aux[n + 1]);
                outf[(size_t)(r + 8) * nOut + n]     = ftanh(v2 + aux[n]);
                outf[(size_t)(r + 8) * nOut + n + 1] = ftanh(v3 + aux[n + 1]);
            } else if (EPI == EPI_TANH_SPLIT) {
#pragma unroll
                for (int q = 0; q < 4; q++) {
                    int rr = (q >= 2) ? r + 8 : r;
                    int nn = n + (q & 1);
                    float v = (q == 0) ? v0 : (q == 1) ? v1 : (q == 2) ? v2 : v3;
                    float h = ftanh(v + aux[nn]);
                    __half hh = hhi(h);
                    outs[(size_t)rr * AGLD + nn] = hh;
                    outs8[(size_t)rr * HID + nn] = to_e4m3((h - __half2float(hh)) * FP8SCALE);
                }
            } else if (EPI == EPI_GELU) {
#pragma unroll
                for (int q = 0; q < 4; q++) {
                    int rr = (q >= 2) ? r + 8 : r;
                    int nn = n + (q & 1);
                    float v = (q == 0) ? v0 : (q == 1) ? v1 : (q == 2) ? v2 : v3;
                    float u = v + aux[nn];
                    outf[(size_t)rr * nOut + nn] = 0.5f * u * (1.f + erff(u * 0.70710678118654752f));
                }
            } else { // EPI_GATES
                float w0 = v0 + aux[(size_t)r * N4 + n];
                float w1 = v1 + aux[(size_t)r * N4 + n + 1];
                float w2 = v2 + aux[(size_t)(r + 8) * N4 + n];
                float w3 = v3 + aux[(size_t)(r + 8) * N4 + n + 1];
                float u0 = __shfl_xor_sync(0xffffffffu, w0, 1);
                float u1 = __shfl_xor_sync(0xffffffffu, w1, 1);
                float u2 = __shfl_xor_sync(0xffffffffu, w2, 1);
                float u3 = __shfl_xor_sync(0xffffffffu, w3, 1);
                if (!(lane & 1)) {   // even lanes own (i,f); lane^1 holds (g,o)
                    int j = n >> 2;
                    lstm_cell(outf, outs, outs8, r, j, w0, w1, u0, u1);
                    lstm_cell(outf, outs, outs8, r + 8, j, w2, w3, u2, u3);
                }
            }
        }
    }
}

// ------------------------- LayerNorm (warp per row) -------------------------
__global__ void ln_kernel(const __half* __restrict__ Ag, const uint8_t* __restrict__ Al,
                          const float* __restrict__ gam, const float* __restrict__ bet) {
    int warp = (blockIdx.x * blockDim.x + threadIdx.x) >> 5;
    int lane = threadIdx.x & 31;
    if (warp >= BATCH) return;
    size_t base = (size_t)warp * AGLD;
    size_t base8 = (size_t)warp * HID;
    float h[32];
    float s = 0.f, ss = 0.f;
#pragma unroll
    for (int i = 0; i < 32; i++) {
        int k = lane + 32 * i;
        float v = __half2float(Ag[base + k]) + from_e4m3(Al[base8 + k]) * FP8INV;
        h[i] = v; s += v; ss += v * v;
    }
#pragma unroll
    for (int o = 16; o; o >>= 1) {
        s  += __shfl_xor_sync(0xffffffffu, s, o);
        ss += __shfl_xor_sync(0xffffffffu, ss, o);
    }
    float mu = s * (1.f / HID);
    float var = ss * (1.f / HID) - mu * mu;
    float inv = rsqrtf(var + 1e-5f);
    size_t ob = (size_t)warp * AFLD;
#pragma unroll
    for (int i = 0; i < 32; i++) {
        int k = lane + 32 * i;
        float y = (h[i] - mu) * inv * gam[k] + bet[k];
        g_Af[ob + k] = hhi(y);
    }
}

// ------------------------- delta / pos head (warp per row) -------------------------
__global__ void delta_kernel(const float* __restrict__ W2, const float* __restrict__ b2,
                             float* __restrict__ out, int t, __half* __restrict__ AgN) {
    int warp = (blockIdx.x * blockDim.x + threadIdx.x) >> 5;
    int lane = threadIdx.x & 31;
    if (warp >= BATCH) return;
    const float* y = g_y2 + (size_t)warp * HID;
    float a0 = 0.f, a1 = 0.f;
#pragma unroll
    for (int i = 0; i < 32; i++) {
        int k = lane + 32 * i;
        float v = y[k];
        a0 += v * W2[k];
        a1 += v * W2[HID + k];
    }
#pragma unroll
    for (int o = 16; o; o >>= 1) {
        a0 += __shfl_xor_sync(0xffffffffu, a0, o);
        a1 += __shfl_xor_sync(0xffffffffu, a1, o);
    }
    if (lane == 0) {
        float d0 = a0 + b2[0], d1 = a1 + b2[1];
        float p0 = g_pos[warp * 2 + 0] + d0;
        float p1 = g_pos[warp * 2 + 1] + d1;
        g_pos[warp * 2 + 0] = p0;
        g_pos[warp * 2 + 1] = p1;
        out[(size_t)warp * (TSTEPS * 2) + t * 2 + 0] = p0;
        out[(size_t)warp * (TSTEPS * 2) + t * 2 + 1] = p1;
        float nn = fmaxf(sqrtf(d0 * d0 + d1 * d1), 1e-6f);
        float e[4] = {d0, d1, d0 / nn, d1 / nn};
        size_t base = (size_t)warp * AGLD;
#pragma unroll
        for (int q = 0; q < 4; q++) {
            AgN[base + EBLK + q]     = hhi(e[q]);
            AgN[base + EBLK + 4 + q] = hlo(e[q]);
        }
    }
}

// ------------------------- host -------------------------
static inline int nb(long n) { return (int)((n + 255) / 256); }

extern "C" void kernel_launch(void* const* d_in, const int* in_sizes, int n_in,
                              void* d_out, int out_size) {
    const float* context    = (const float*)d_in[0];
    const float* last_pos   = (const float*)d_in[1];
    const float* last_delta = (const float*)d_in[2];
    const float* Wh   = (const float*)d_in[3];
    const float* bh   = (const float*)d_in[4];
    const float* Wc   = (const float*)d_in[5];
    const float* bc   = (const float*)d_in[6];
    const float* W_ih = (const float*)d_in[7];
    const float* b_ih = (const float*)d_in[8];
    const float* W_hh = (const float*)d_in[9];
    const float* b_hh = (const float*)d_in[10];
    const float* ln_g = (const float*)d_in[11];
    const float* ln_b = (const float*)d_in[12];
    const float* W1   = (const float*)d_in[13];
    const float* b1   = (const float*)d_in[14];
    const float* W2   = (const float*)d_in[15];
    const float* b2   = (const float*)d_in[16];
    float* out = (float*)d_out;

    __half *pCtxs, *pAg0, *pAg1, *pAf, *pWg, *pWc4, *pWhh, *pWcc, *pW1s;
    uint8_t *pAl0, *pAl1, *pWq;
    float *pGctx, *pC, *pY2, *pBsum;
    cudaGetSymbolAddress((void**)&pCtxs, g_ctxs);
    cudaGetSymbolAddress((void**)&pAg0, g_Ag0);
    cudaGetSymbolAddress((void**)&pAg1, g_Ag1);
    cudaGetSymbolAddress((void**)&pAl0, g_Al0);
    cudaGetSymbolAddress((void**)&pAl1, g_Al1);
    cudaGetSymbolAddress((void**)&pAf,  g_Af);
    cudaGetSymbolAddress((void**)&pWg,  g_Wg);
    cudaGetSymbolAddress((void**)&pWq,  g_Wq);
    cudaGetSymbolAddress((void**)&pWc4, g_Wc4);
    cudaGetSymbolAddress((void**)&pWhh, g_Whh);
    cudaGetSymbolAddress((void**)&pWcc, g_Wcc);
    cudaGetSymbolAddress((void**)&pW1s, g_W1s);
    cudaGetSymbolAddress((void**)&pGctx, g_gctx);
    cudaGetSymbolAddress((void**)&pC,   g_c);
    cudaGetSymbolAddress((void**)&pY2,  g_y2);
    cudaGetSymbolAddress((void**)&pBsum, g_bsum);

    cudaFuncSetAttribute(gemm2<EPI_CTX>,        cudaFuncAttributeMaxDynamicSharedMemorySize, GEMM_SMEM);
    cudaFuncSetAttribute(gemm2<EPI_TANH_SPLIT>, cudaFuncAttributeMaxDynamicSharedMemorySize, GEMM_SMEM);
    cudaFuncSetAttribute(gemm2<EPI_TANH_C>,     cudaFuncAttributeMaxDynamicSharedMemorySize, GEMM_SMEM);
    cudaFuncSetAttribute(gemm2<EPI_GATES>,      cudaFuncAttributeMaxDynamicSharedMemorySize, GEMM_SMEM);
    cudaFuncSetAttribute(gemm2<EPI_GELU>,       cudaFuncAttributeMaxDynamicSharedMemorySize, GEMM_SMEM);

    const int BIG = 1 << 30;

    {
        long tot = (long)N4 * KG16 + (long)N4 * HID + (long)N4 * KC + N4
                 + (long)HID * CTXK * 2 + (long)HID * HID;
        prep_weights<<<nb(tot), 256>>>(W_hh, W_ih, b_ih, b_hh, Wh, Wc, W1);
    }
    {
        long tot = (long)BATCH * CTXK + BATCH;
        prep_data<<<nb(tot), 256>>>(context, last_pos, last_delta);
    }

    dim3 blk(256);
    dim3 grid_n4(N4 / 128, BATCH / 128);   // (32,128)
    dim3 grid_h(HID / 128, BATCH / 128);   // (8,128)

    // gates_ctx (3-term fp16), hidden/cell init (3-term fp16)
    gemm2<EPI_CTX><<<grid_n4, blk, GEMM_SMEM>>>(pCtxs, ACLD, nullptr, pWc4, KC, nullptr,
                                                KC / 64, KC / 64, 1024, 1024,
                                                pBsum, pGctx, nullptr, nullptr, N4);
    gemm2<EPI_TANH_SPLIT><<<grid_h, blk, GEMM_SMEM>>>(pCtxs, ACLD, nullptr, pWhh, KC, nullptr,
                                                      KC / 64, KC / 64, 1024, 1024,
                                                      bh, nullptr, pAg0, pAl0, HID);
    gemm2<EPI_TANH_C><<<grid_h, blk, GEMM_SMEM>>>(pCtxs, ACLD, nullptr, pWcc, KC, nullptr,
                                                  KC / 64, KC / 64, 1024, 1024,
                                                  bc, pC, nullptr, nullptr, HID);

    __half* Ag[2] = {pAg0, pAg1};
    uint8_t* Al[2] = {pAl0, pAl1};
    for (int t = 0; t < TSTEPS; t++) {
        int cur = t & 1, nxt = cur ^ 1;
        gemm2<EPI_GATES><<<grid_n4, blk, GEMM_SMEM>>>(Ag[cur], AGLD, Al[cur], pWg, KG16, pWq,
                                                      NKG, KSG, BIG, 0,
                                                      pGctx, pC, Ag[nxt], Al[nxt], N4);
        ln_kernel<<<BATCH / 8, 256>>>(Ag[nxt], Al[nxt], ln_g, ln_b);
        gemm2<EPI_GELU><<<grid_h, blk, GEMM_SMEM>>>(pAf, AFLD, nullptr, pW1s, KF, nullptr,
                                                    KF / 64, KF / 64, BIG, 0,
                                                    b1, pY2, nullptr, nullptr, HID);
        delta_kernel<<<BATCH / 8, 256>>>(W2, b2, out, t, Ag[nxt]);
    }
}

// round 13
// speedup vs baseline: 1.1724x; 1.1724x over previous
#include <cuda_runtime.h>
#include <cuda_fp16.h>
#include <math.h>
#include <stdint.h>

#define BATCH   16384
#define HID     1024
#define CTXK    512
#define N4      4096
#define TSTEPS  60
#define INW     516     // W_ih row width (C+4)

// gates GEMM (fp16 2-term): A row = K row = [h_hi(1024) | h_lo(1024)] -> KG=2048
// extra term e(4)x We(4,n) applied in the epilogue from g_e / g_We (fp32).
#define AGLD    2048
#define KG      2048
// ffn GEMM (single-term fp16): A row = K row = [y(1024)]
#define AFLD    1024
#define KF      1024
// context GEMMs (one-time, 3-term fp16): A row = [c_hi(512)|c_lo(512)];
//   K = [c_hi | c_lo | c_hi(re-read)] = 1536 ; W = [W_hi|W_hi|W_lo]
#define ACLD    1024
#define KC      1536

// ------------------------- scratch (device globals) -------------------------
__device__ __align__(256) float   g_gctx[(size_t)BATCH * N4];
__device__ __align__(256) __half  g_Ag0[(size_t)BATCH * AGLD];
__device__ __align__(256) __half  g_Ag1[(size_t)BATCH * AGLD];
__device__ __align__(256) __half  g_Af [(size_t)BATCH * AFLD];
__device__ __align__(256) __half  g_ctxs[(size_t)BATCH * ACLD];
__device__ __align__(256) float   g_c  [(size_t)BATCH * HID];
__device__ __align__(256) float   g_y2 [(size_t)BATCH * HID];
__device__ __align__(256) float   g_pos[(size_t)BATCH * 2];
__device__ __align__(256) float   g_e  [(size_t)BATCH * 4];       // [pd0,pd1,hd0,hd1]
__device__ __align__(256) float   g_We [(size_t)N4 * 4];          // permuted W_extra
__device__ __align__(256) __half  g_Wg  [(size_t)N4 * KG];
__device__ __align__(256) __half  g_Wc4 [(size_t)N4 * KC];
__device__ __align__(256) __half  g_Whh [(size_t)HID * KC];
__device__ __align__(256) __half  g_Wcc [(size_t)HID * KC];
__device__ __align__(256) __half  g_W1s [(size_t)HID * KF];
__device__ __align__(256) float   g_bsum[N4];

// ------------------------- low-level helpers -------------------------
#define SW128(b) ((b) ^ (((b) >> 3) & 0x70))

__device__ __forceinline__ void cpasync16(uint32_t dst, const void* src) {
    asm volatile("cp.async.cg.shared.global [%0],[%1],16;\n" :: "r"(dst), "l"(src));
}
__device__ __forceinline__ void ldsm4(uint32_t* r, uint32_t addr) {
    asm volatile("ldmatrix.sync.aligned.m8n8.x4.shared.b16 {%0,%1,%2,%3}, [%4];"
                 : "=r"(r[0]), "=r"(r[1]), "=r"(r[2]), "=r"(r[3]) : "r"(addr));
}
__device__ __forceinline__ void mma16816(float* c, const uint32_t* a, const uint32_t* b) {
    asm volatile(
        "mma.sync.aligned.m16n8k16.row.col.f32.f16.f16.f32 "
        "{%0,%1,%2,%3},{%4,%5,%6,%7},{%8,%9},{%0,%1,%2,%3};\n"
        : "+f"(c[0]), "+f"(c[1]), "+f"(c[2]), "+f"(c[3])
        : "r"(a[0]), "r"(a[1]), "r"(a[2]), "r"(a[3]), "r"(b[0]), "r"(b[1]));
}
__device__ __forceinline__ __half hhi(float v) { return __float2half_rn(v); }
__device__ __forceinline__ __half hlo(float v) {
    return __float2half_rn(v - __half2float(__float2half_rn(v)));
}
// fast activations: __expf (MUFU.EX2) + __fdividef (MUFU.RCP), rel err ~2^-21
__device__ __forceinline__ float fsig(float x) {
    return __fdividef(1.f, 1.f + __expf(-x));
}
__device__ __forceinline__ float ftanh(float x) {
    return 1.f - __fdividef(2.f, __expf(2.f * x) + 1.f);   // exact identity
}

// ------------------------- prep kernels -------------------------
__global__ void prep_weights(const float* __restrict__ Whh, const float* __restrict__ Wih,
                             const float* __restrict__ b_ih, const float* __restrict__ b_hh,
                             const float* __restrict__ Wh, const float* __restrict__ Wc,
                             const float* __restrict__ W1) {
    const long n_wg = (long)N4 * KG;
    const long n_wc = (long)N4 * KC;
    const long n_s  = (long)HID * CTXK;
    const long n_w1 = (long)HID * HID;
    long i = (long)blockIdx.x * blockDim.x + threadIdx.x;

    if (i < n_wg) {   // [Whh_hi | Whh_hi] (2-term: lo section of A pairs with same W_hi)
        int np = (int)(i / KG), k = (int)(i % KG);
        int r = (np & 3) * HID + (np >> 2);
        float w = (k < 1024) ? Whh[(size_t)r * HID + k]
                             : Whh[(size_t)r * HID + (k - 1024)];
        g_Wg[(size_t)np * KG + k] = hhi(w);
        return;
    }
    i -= n_wg;
    if (i < N4 * 4) { // W_extra permuted fp32 table [np][4]
        int np = (int)(i >> 2), q = (int)(i & 3);
        int r = (np & 3) * HID + (np >> 2);
        g_We[(size_t)np * 4 + q] = Wih[(size_t)r * INW + CTXK + q];
        return;
    }
    i -= N4 * 4;
    if (i < n_wc) {   // W_ih ctx part (3-term): [hi(512)|hi(512)|lo(512)]
        int np = (int)(i / KC), k = (int)(i % KC);
        int r = (np & 3) * HID + (np >> 2);
        int src = (k < 512) ? k : (k < 1024 ? k - 512 : k - 1024);
        float w = Wih[(size_t)r * INW + src];
        g_Wc4[(size_t)np * KC + k] = (k < 1024) ? hhi(w) : hlo(w);
        return;
    }
    i -= n_wc;
    if (i < N4) {
        int r = ((int)i & 3) * HID + ((int)i >> 2);
        g_bsum[i] = b_ih[r] + b_hh[r];
        return;
    }
    i -= N4;
    if (i < n_s) {    // Wh (3-term): [hi|hi|lo]
        int r = (int)(i / CTXK), k = (int)(i % CTXK);
        float w = Wh[(size_t)r * CTXK + k];
        size_t b = (size_t)r * KC;
        g_Whh[b + k] = hhi(w); g_Whh[b + 512 + k] = hhi(w); g_Whh[b + 1024 + k] = hlo(w);
        return;
    }
    i -= n_s;
    if (i < n_s) {    // Wc (3-term)
        int r = (int)(i / CTXK), k = (int)(i % CTXK);
        float w = Wc[(size_t)r * CTXK + k];
        size_t b = (size_t)r * KC;
        g_Wcc[b + k] = hhi(w); g_Wcc[b + 512 + k] = hhi(w); g_Wcc[b + 1024 + k] = hlo(w);
        return;
    }
    i -= n_s;
    if (i < n_w1) {   // W1 (single-term fp16)
        int r = (int)(i / HID), k = (int)(i % HID);
        g_W1s[(size_t)r * KF + k] = hhi(W1[(size_t)r * HID + k]);
    }
}

__global__ void prep_data(const float* __restrict__ ctx,
                          const float* __restrict__ last_pos,
                          const float* __restrict__ last_delta) {
    const long n_cs = (long)BATCH * CTXK;
    long i = (long)blockIdx.x * blockDim.x + threadIdx.x;
    if (i < n_cs) {
        int b = (int)(i / CTXK), k = (int)(i % CTXK);
        float v = ctx[i];
        g_ctxs[(size_t)b * ACLD + k]       = hhi(v);
        g_ctxs[(size_t)b * ACLD + 512 + k] = hlo(v);
        return;
    }
    i -= n_cs;
    if (i < BATCH) {
        int b = (int)i;
        g_pos[b * 2 + 0] = last_pos[b * 2 + 0];
        g_pos[b * 2 + 1] = last_pos[b * 2 + 1];
        float d0 = last_delta[b * 2 + 0], d1 = last_delta[b * 2 + 1];
        float nn = fmaxf(sqrtf(d0 * d0 + d1 * d1), 1e-6f);
        g_e[b * 4 + 0] = d0;
        g_e[b * 4 + 1] = d1;
        g_e[b * 4 + 2] = d0 / nn;
        g_e[b * 4 + 3] = d1 / nn;
    }
}

// ------------------------- GEMM engine (R6/R8-proven 128x128) -------------------------
// 128x128 CTA tile, KTILE=64, 3-slot ring / 2 tiles in flight, ldmatrix,
// one __syncthreads per K-tile. 256 threads, warp grid 2Mx4N, warp tile 64x32.
#define TK 64
#define NSTG 3
#define STG_BYTES 32768          // A 16KB + B 16KB
#define GEMM_SMEM (NSTG * STG_BYTES)

enum { EPI_CTX = 0, EPI_TANH_SPLIT = 1, EPI_TANH_C = 2, EPI_GATES = 3, EPI_GELU = 4 };

__device__ __forceinline__ void lstm_cell(float* cbuf, __half* outs, int row, int j,
                                          float gi, float gf, float gg, float go) {
    float cold = cbuf[(size_t)row * HID + j];
    float si = fsig(gi);
    float sf = fsig(gf);
    float so = fsig(go);
    float tg = ftanh(gg);
    float cn = sf * cold + si * tg;
    float h  = so * ftanh(cn);
    cbuf[(size_t)row * HID + j] = cn;
    outs[(size_t)row * AGLD + j]        = hhi(h);
    outs[(size_t)row * AGLD + 1024 + j] = hlo(h);
}

template <int EPI>
__global__ void __launch_bounds__(256, 2)
gemm2(const __half* __restrict__ A, int lda,
      const __half* __restrict__ W, int ktot,
      int s1, int d1,                        // K->A col mapping (per 64-tile)
      const float* __restrict__ aux,
      float* __restrict__ outf,
      __half* __restrict__ outs,
      int nOut) {
    extern __shared__ __align__(1024) char smp[];
    const uint32_t sbase = (uint32_t)__cvta_generic_to_shared(smp);

    const int tid = threadIdx.x;
    const int lane = tid & 31, wid = tid >> 5;
    const int wm = wid >> 2, wn = wid & 3;
    const int m0 = blockIdx.y * 128, n0 = blockIdx.x * 128;
    const int nK = ktot / TK;

    float acc[4][4][4];
#pragma unroll
    for (int a = 0; a < 4; a++)
#pragma unroll
        for (int b = 0; b < 4; b++)
#pragma unroll
            for (int c = 0; c < 4; c++) acc[a][b][c] = 0.f;

    auto fill = [&](int kt) {
        int slot = kt % NSTG;
        uint32_t sA = sbase + slot * STG_BYTES;
        uint32_t sB = sA + 16384;
        int k0 = kt * TK;
        int cb = (k0 < s1) ? k0 : k0 - d1;
#pragma unroll
        for (int t = 0; t < 4; t++) {
            int c = tid + t * 256;
            int row = c >> 3, ch = c & 7;
            cpasync16(sA + SW128(row * 128 + ch * 16),
                      A + (size_t)(m0 + row) * lda + cb + ch * 8);
        }
#pragma unroll
        for (int t = 0; t < 4; t++) {
            int c = tid + t * 256;
            int row = c >> 3, ch = c & 7;
            cpasync16(sB + SW128(row * 128 + ch * 16),
                      W + (size_t)(n0 + row) * ktot + k0 + ch * 8);
        }
        asm volatile("cp.async.commit_group;\n");
    };

    // prologue: 2 tiles in flight
    fill(0);
    if (nK > 1) fill(1);

    const int g  = lane >> 3;
    const int lr = lane & 7;

    for (int kt = 0; kt < nK; kt++) {
        if (kt + 1 < nK) asm volatile("cp.async.wait_group 1;\n");
        else             asm volatile("cp.async.wait_group 0;\n");
        __syncthreads();                       // all warps done reading slot (kt-1)%3
        if (kt + 2 < nK) fill(kt + 2);         // safe: overwrites slot (kt-1)%3

        int slot = kt % NSTG;
        uint32_t sA = sbase + slot * STG_BYTES;
        uint32_t sB = sA + 16384;

#pragma unroll
        for (int ks = 0; ks < 4; ks++) {
            uint32_t a[4][4], b[2][4];
#pragma unroll
            for (int mf = 0; mf < 4; mf++) {
                int row = wm * 64 + mf * 16 + lr + ((g & 1) << 3);
                ldsm4(a[mf], sA + SW128(row * 128 + ks * 32 + ((g >> 1) << 4)));
            }
#pragma unroll
            for (int nf = 0; nf < 2; nf++) {
                int row = wn * 32 + nf * 16 + lr + ((g >> 1) << 3);
                ldsm4(b[nf], sB + SW128(row * 128 + ks * 32 + ((g & 1) << 4)));
            }
#pragma unroll
            for (int mf = 0; mf < 4; mf++) {
#pragma unroll
                for (int nf = 0; nf < 2; nf++) {
                    mma16816(acc[mf][2 * nf],     a[mf], &b[nf][0]);
                    mma16816(acc[mf][2 * nf + 1], a[mf], &b[nf][2]);
                }
            }
        }
    }

    // ------------------------- epilogue -------------------------
#pragma unroll
    for (int mt = 0; mt < 4; mt++) {
#pragma unroll
        for (int nt = 0; nt < 4; nt++) {
            int r = m0 + wm * 64 + mt * 16 + (lane >> 2);
            int n = n0 + wn * 32 + nt * 8 + (lane & 3) * 2;
            float v0 = acc[mt][nt][0], v1 = acc[mt][nt][1];
            float v2 = acc[mt][nt][2], v3 = acc[mt][nt][3];

            if (EPI == EPI_CTX) {
                outf[(size_t)r * nOut + n]           = v0 + aux[n];
                outf[(size_t)r * nOut + n + 1]       = v1 + aux[n + 1];
                outf[(size_t)(r + 8) * nOut + n]     = v2 + aux[n];
                outf[(size_t)(r + 8) * nOut + n + 1] = v3 + aux[n + 1];
            } else if (EPI == EPI_TANH_C) {
                outf[(size_t)r * nOut + n]           = ftanh(v0 + aux[n]);
                outf[(size_t)r * nOut + n + 1]       = ftanh(v1 + aux[n + 1]);
                outf[(size_t)(r + 8) * nOut + n]     = ftanh(v2 + aux[n]);
                outf[(size_t)(r + 8) * nOut + n + 1] = ftanh(v3 + aux[n + 1]);
            } else if (EPI == EPI_TANH_SPLIT) {
#pragma unroll
                for (int q = 0; q < 4; q++) {
                    int rr = (q >= 2) ? r + 8 : r;
                    int nn = n + (q & 1);
                    float v = (q == 0) ? v0 : (q == 1) ? v1 : (q == 2) ? v2 : v3;
                    float h = ftanh(v + aux[nn]);
                    outs[(size_t)rr * AGLD + nn]        = hhi(h);
                    outs[(size_t)rr * AGLD + 1024 + nn] = hlo(h);
                }
            } else if (EPI == EPI_GELU) {
#pragma unroll
                for (int q = 0; q < 4; q++) {
                    int rr = (q >= 2) ? r + 8 : r;
                    int nn = n + (q & 1);
                    float v = (q == 0) ? v0 : (q == 1) ? v1 : (q == 2) ? v2 : v3;
                    float u = v + aux[nn];
                    outf[(size_t)rr * nOut + nn] = 0.5f * u * (1.f + erff(u * 0.70710678118654752f));
                }
            } else { // EPI_GATES: add gctx + rank-4 extra term, then LSTM cell
                float4 e0 = *(const float4*)(g_e + (size_t)r * 4);
                float4 e1 = *(const float4*)(g_e + (size_t)(r + 8) * 4);
                float4 wa = *(const float4*)(g_We + (size_t)n * 4);
                float4 wb = *(const float4*)(g_We + (size_t)(n + 1) * 4);
                float xa0 = e0.x * wa.x + e0.y * wa.y + e0.z * wa.z + e0.w * wa.w;
                float xb0 = e0.x * wb.x + e0.y * wb.y + e0.z * wb.z + e0.w * wb.w;
                float xa1 = e1.x * wa.x + e1.y * wa.y + e1.z * wa.z + e1.w * wa.w;
                float xb1 = e1.x * wb.x + e1.y * wb.y + e1.z * wb.z + e1.w * wb.w;
                float w0 = v0 + aux[(size_t)r * N4 + n]           + xa0;
                float w1 = v1 + aux[(size_t)r * N4 + n + 1]       + xb0;
                float w2 = v2 + aux[(size_t)(r + 8) * N4 + n]     + xa1;
                float w3 = v3 + aux[(size_t)(r + 8) * N4 + n + 1] + xb1;
                float u0 = __shfl_xor_sync(0xffffffffu, w0, 1);
                float u1 = __shfl_xor_sync(0xffffffffu, w1, 1);
                float u2 = __shfl_xor_sync(0xffffffffu, w2, 1);
                float u3 = __shfl_xor_sync(0xffffffffu, w3, 1);
                if (!(lane & 1)) {   // even lanes own (i,f); lane^1 holds (g,o)
                    int j = n >> 2;
                    lstm_cell(outf, outs, r, j, w0, w1, u0, u1);
                    lstm_cell(outf, outs, r + 8, j, w2, w3, u2, u3);
                }
            }
        }
    }
}

// ------------------------- LayerNorm (warp per row) -------------------------
__global__ void ln_kernel(const __half* __restrict__ Ag,
                          const float* __restrict__ gam, const float* __restrict__ bet) {
    int warp = (blockIdx.x * blockDim.x + threadIdx.x) >> 5;
    int lane = threadIdx.x & 31;
    if (warp >= BATCH) return;
    size_t base = (size_t)warp * AGLD;
    float h[32];
    float s = 0.f, ss = 0.f;
#pragma unroll
    for (int i = 0; i < 32; i++) {
        int k = lane + 32 * i;
        float v = __half2float(Ag[base + k]) + __half2float(Ag[base + 1024 + k]);
        h[i] = v; s += v; ss += v * v;
    }
#pragma unroll
    for (int o = 16; o; o >>= 1) {
        s  += __shfl_xor_sync(0xffffffffu, s, o);
        ss += __shfl_xor_sync(0xffffffffu, ss, o);
    }
    float mu = s * (1.f / HID);
    float var = ss * (1.f / HID) - mu * mu;
    float inv = rsqrtf(var + 1e-5f);
    size_t ob = (size_t)warp * AFLD;
#pragma unroll
    for (int i = 0; i < 32; i++) {
        int k = lane + 32 * i;
        float y = (h[i] - mu) * inv * gam[k] + bet[k];
        g_Af[ob + k] = hhi(y);
    }
}

// ------------------------- delta / pos head (warp per row) -------------------------
__global__ void delta_kernel(const float* __restrict__ W2, const float* __restrict__ b2,
                             float* __restrict__ out, int t) {
    int warp = (blockIdx.x * blockDim.x + threadIdx.x) >> 5;
    int lane = threadIdx.x & 31;
    if (warp >= BATCH) return;
    const float* y = g_y2 + (size_t)warp * HID;
    float a0 = 0.f, a1 = 0.f;
#pragma unroll
    for (int i = 0; i < 32; i++) {
        int k = lane + 32 * i;
        float v = y[k];
        a0 += v * W2[k];
        a1 += v * W2[HID + k];
    }
#pragma unroll
    for (int o = 16; o; o >>= 1) {
        a0 += __shfl_xor_sync(0xffffffffu, a0, o);
        a1 += __shfl_xor_sync(0xffffffffu, a1, o);
    }
    if (lane == 0) {
        float d0 = a0 + b2[0], d1 = a1 + b2[1];
        float p0 = g_pos[warp * 2 + 0] + d0;
        float p1 = g_pos[warp * 2 + 1] + d1;
        g_pos[warp * 2 + 0] = p0;
        g_pos[warp * 2 + 1] = p1;
        out[(size_t)warp * (TSTEPS * 2) + t * 2 + 0] = p0;
        out[(size_t)warp * (TSTEPS * 2) + t * 2 + 1] = p1;
        float nn = fmaxf(sqrtf(d0 * d0 + d1 * d1), 1e-6f);
        g_e[warp * 4 + 0] = d0;
        g_e[warp * 4 + 1] = d1;
        g_e[warp * 4 + 2] = d0 / nn;
        g_e[warp * 4 + 3] = d1 / nn;
    }
}

// ------------------------- host -------------------------
static inline int nb(long n) { return (int)((n + 255) / 256); }

extern "C" void kernel_launch(void* const* d_in, const int* in_sizes, int n_in,
                              void* d_out, int out_size) {
    const float* context    = (const float*)d_in[0];
    const float* last_pos   = (const float*)d_in[1];
    const float* last_delta = (const float*)d_in[2];
    const float* Wh   = (const float*)d_in[3];
    const float* bh   = (const float*)d_in[4];
    const float* Wc   = (const float*)d_in[5];
    const float* bc   = (const float*)d_in[6];
    const float* W_ih = (const float*)d_in[7];
    const float* b_ih = (const float*)d_in[8];
    const float* W_hh = (const float*)d_in[9];
    const float* b_hh = (const float*)d_in[10];
    const float* ln_g = (const float*)d_in[11];
    const float* ln_b = (const float*)d_in[12];
    const float* W1   = (const float*)d_in[13];
    const float* b1   = (const float*)d_in[14];
    const float* W2   = (const float*)d_in[15];
    const float* b2   = (const float*)d_in[16];
    float* out = (float*)d_out;

    __half *pCtxs, *pAg0, *pAg1, *pAf, *pWg, *pWc4, *pWhh, *pWcc, *pW1s;
    float *pGctx, *pC, *pY2, *pBsum;
    cudaGetSymbolAddress((void**)&pCtxs, g_ctxs);
    cudaGetSymbolAddress((void**)&pAg0, g_Ag0);
    cudaGetSymbolAddress((void**)&pAg1, g_Ag1);
    cudaGetSymbolAddress((void**)&pAf,  g_Af);
    cudaGetSymbolAddress((void**)&pWg,  g_Wg);
    cudaGetSymbolAddress((void**)&pWc4, g_Wc4);
    cudaGetSymbolAddress((void**)&pWhh, g_Whh);
    cudaGetSymbolAddress((void**)&pWcc, g_Wcc);
    cudaGetSymbolAddress((void**)&pW1s, g_W1s);
    cudaGetSymbolAddress((void**)&pGctx, g_gctx);
    cudaGetSymbolAddress((void**)&pC,   g_c);
    cudaGetSymbolAddress((void**)&pY2,  g_y2);
    cudaGetSymbolAddress((void**)&pBsum, g_bsum);

    cudaFuncSetAttribute(gemm2<EPI_CTX>,        cudaFuncAttributeMaxDynamicSharedMemorySize, GEMM_SMEM);
    cudaFuncSetAttribute(gemm2<EPI_TANH_SPLIT>, cudaFuncAttributeMaxDynamicSharedMemorySize, GEMM_SMEM);
    cudaFuncSetAttribute(gemm2<EPI_TANH_C>,     cudaFuncAttributeMaxDynamicSharedMemorySize, GEMM_SMEM);
    cudaFuncSetAttribute(gemm2<EPI_GATES>,      cudaFuncAttributeMaxDynamicSharedMemorySize, GEMM_SMEM);
    cudaFuncSetAttribute(gemm2<EPI_GELU>,       cudaFuncAttributeMaxDynamicSharedMemorySize, GEMM_SMEM);

    const int BIG = 1 << 30;

    {
        long tot = (long)N4 * KG + (long)N4 * 4 + (long)N4 * KC + N4
                 + (long)HID * CTXK * 2 + (long)HID * HID;
        prep_weights<<<nb(tot), 256>>>(W_hh, W_ih, b_ih, b_hh, Wh, Wc, W1);
    }
    {
        long tot = (long)BATCH * CTXK + BATCH;
        prep_data<<<nb(tot), 256>>>(context, last_pos, last_delta);
    }

    dim3 blk(256);
    dim3 grid_n4(N4 / 128, BATCH / 128);   // (32,128)
    dim3 grid_h(HID / 128, BATCH / 128);   // (8,128)

    // gates_ctx (3-term), hidden/cell init (3-term)
    gemm2<EPI_CTX><<<grid_n4, blk, GEMM_SMEM>>>(pCtxs, ACLD, pWc4, KC, 1024, 1024,
                                                pBsum, pGctx, nullptr, N4);
    gemm2<EPI_TANH_SPLIT><<<grid_h, blk, GEMM_SMEM>>>(pCtxs, ACLD, pWhh, KC, 1024, 1024,
                                                      bh, nullptr, pAg0, HID);
    gemm2<EPI_TANH_C><<<grid_h, blk, GEMM_SMEM>>>(pCtxs, ACLD, pWcc, KC, 1024, 1024,
                                                  bc, pC, nullptr, HID);

    __half* Ag[2] = {pAg0, pAg1};
    for (int t = 0; t < TSTEPS; t++) {
        int cur = t & 1, nxt = cur ^ 1;
        gemm2<EPI_GATES><<<grid_n4, blk, GEMM_SMEM>>>(Ag[cur], AGLD, pWg, KG, BIG, 0,
                                                      pGctx, pC, Ag[nxt], N4);
        ln_kernel<<<BATCH / 8, 256>>>(Ag[nxt], ln_g, ln_b);
        gemm2<EPI_GELU><<<grid_h, blk, GEMM_SMEM>>>(pAf, AFLD, pW1s, KF, BIG, 0,
                                                    b1, pY2, nullptr, HID);
        delta_kernel<<<BATCH / 8, 256>>>(W2, b2, out, t);
    }
}

// round 14
// speedup vs baseline: 1.7099x; 1.4585x over previous
#include <cuda_runtime.h>
#include <cuda_fp16.h>
#include <math.h>
#include <stdint.h>

#define BATCH   16384
#define HID     1024
#define CTXK    512
#define N4      4096
#define TSTEPS  60
#define INW     516     // W_ih row width (C+4)

// gates GEMM (single-term fp16): A row = K row = [h_hi(1024)] -> KG=1024
// extra term e(4)x We(4,n) applied in the epilogue from g_e / g_We (fp32).
#define AGLD    1024
#define KG      1024
// ffn GEMM (single-term fp16): A row = K row = [y(1024)]
#define AFLD    1024
#define KF      1024
// context GEMMs (one-time, 3-term fp16): A row = [c_hi(512)|c_lo(512)];
//   K = [c_hi | c_lo | c_hi(re-read)] = 1536 ; W = [W_hi|W_hi|W_lo]
#define ACLD    1024
#define KC      1536

// ------------------------- scratch (device globals) -------------------------
__device__ __align__(256) float   g_gctx[(size_t)BATCH * N4];
__device__ __align__(256) __half  g_Ag0[(size_t)BATCH * AGLD];
__device__ __align__(256) __half  g_Ag1[(size_t)BATCH * AGLD];
__device__ __align__(256) __half  g_Af [(size_t)BATCH * AFLD];
__device__ __align__(256) __half  g_ctxs[(size_t)BATCH * ACLD];
__device__ __align__(256) float   g_c  [(size_t)BATCH * HID];
__device__ __align__(256) float   g_y2 [(size_t)BATCH * HID];
__device__ __align__(256) float   g_pos[(size_t)BATCH * 2];
__device__ __align__(256) float   g_e  [(size_t)BATCH * 4];       // [pd0,pd1,hd0,hd1]
__device__ __align__(256) float   g_We [(size_t)N4 * 4];          // permuted W_extra
__device__ __align__(256) __half  g_Wg  [(size_t)N4 * KG];
__device__ __align__(256) __half  g_Wc4 [(size_t)N4 * KC];
__device__ __align__(256) __half  g_Whh [(size_t)HID * KC];
__device__ __align__(256) __half  g_Wcc [(size_t)HID * KC];
__device__ __align__(256) __half  g_W1s [(size_t)HID * KF];
__device__ __align__(256) float   g_bsum[N4];

// ------------------------- low-level helpers -------------------------
#define SW128(b) ((b) ^ (((b) >> 3) & 0x70))

__device__ __forceinline__ void cpasync16(uint32_t dst, const void* src) {
    asm volatile("cp.async.cg.shared.global [%0],[%1],16;\n" :: "r"(dst), "l"(src));
}
__device__ __forceinline__ void ldsm4(uint32_t* r, uint32_t addr) {
    asm volatile("ldmatrix.sync.aligned.m8n8.x4.shared.b16 {%0,%1,%2,%3}, [%4];"
                 : "=r"(r[0]), "=r"(r[1]), "=r"(r[2]), "=r"(r[3]) : "r"(addr));
}
__device__ __forceinline__ void mma16816(float* c, const uint32_t* a, const uint32_t* b) {
    asm volatile(
        "mma.sync.aligned.m16n8k16.row.col.f32.f16.f16.f32 "
        "{%0,%1,%2,%3},{%4,%5,%6,%7},{%8,%9},{%0,%1,%2,%3};\n"
        : "+f"(c[0]), "+f"(c[1]), "+f"(c[2]), "+f"(c[3])
        : "r"(a[0]), "r"(a[1]), "r"(a[2]), "r"(a[3]), "r"(b[0]), "r"(b[1]));
}
__device__ __forceinline__ __half hhi(float v) { return __float2half_rn(v); }
__device__ __forceinline__ __half hlo(float v) {
    return __float2half_rn(v - __half2float(__float2half_rn(v)));
}
// fast activations: __expf (MUFU.EX2) + __fdividef (MUFU.RCP), rel err ~2^-21
__device__ __forceinline__ float fsig(float x) {
    return __fdividef(1.f, 1.f + __expf(-x));
}
__device__ __forceinline__ float ftanh(float x) {
    return 1.f - __fdividef(2.f, __expf(2.f * x) + 1.f);   // exact identity
}

// ------------------------- prep kernels -------------------------
__global__ void prep_weights(const float* __restrict__ Whh, const float* __restrict__ Wih,
                             const float* __restrict__ b_ih, const float* __restrict__ b_hh,
                             const float* __restrict__ Wh, const float* __restrict__ Wc,
                             const float* __restrict__ W1) {
    const long n_wg = (long)N4 * KG;
    const long n_wc = (long)N4 * KC;
    const long n_s  = (long)HID * CTXK;
    const long n_w1 = (long)HID * HID;
    long i = (long)blockIdx.x * blockDim.x + threadIdx.x;

    if (i < n_wg) {   // single-term: Whh_hi, rows permuted n'=4j+g
        int np = (int)(i / KG), k = (int)(i % KG);
        int r = (np & 3) * HID + (np >> 2);
        g_Wg[(size_t)np * KG + k] = hhi(Whh[(size_t)r * HID + k]);
        return;
    }
    i -= n_wg;
    if (i < N4 * 4) { // W_extra permuted fp32 table [np][4]
        int np = (int)(i >> 2), q = (int)(i & 3);
        int r = (np & 3) * HID + (np >> 2);
        g_We[(size_t)np * 4 + q] = Wih[(size_t)r * INW + CTXK + q];
        return;
    }
    i -= N4 * 4;
    if (i < n_wc) {   // W_ih ctx part (3-term): [hi(512)|hi(512)|lo(512)]
        int np = (int)(i / KC), k = (int)(i % KC);
        int r = (np & 3) * HID + (np >> 2);
        int src = (k < 512) ? k : (k < 1024 ? k - 512 : k - 1024);
        float w = Wih[(size_t)r * INW + src];
        g_Wc4[(size_t)np * KC + k] = (k < 1024) ? hhi(w) : hlo(w);
        return;
    }
    i -= n_wc;
    if (i < N4) {
        int r = ((int)i & 3) * HID + ((int)i >> 2);
        g_bsum[i] = b_ih[r] + b_hh[r];
        return;
    }
    i -= N4;
    if (i < n_s) {    // Wh (3-term): [hi|hi|lo]
        int r = (int)(i / CTXK), k = (int)(i % CTXK);
        float w = Wh[(size_t)r * CTXK + k];
        size_t b = (size_t)r * KC;
        g_Whh[b + k] = hhi(w); g_Whh[b + 512 + k] = hhi(w); g_Whh[b + 1024 + k] = hlo(w);
        return;
    }
    i -= n_s;
    if (i < n_s) {    // Wc (3-term)
        int r = (int)(i / CTXK), k = (int)(i % CTXK);
        float w = Wc[(size_t)r * CTXK + k];
        size_t b = (size_t)r * KC;
        g_Wcc[b + k] = hhi(w); g_Wcc[b + 512 + k] = hhi(w); g_Wcc[b + 1024 + k] = hlo(w);
        return;
    }
    i -= n_s;
    if (i < n_w1) {   // W1 (single-term fp16)
        int r = (int)(i / HID), k = (int)(i % HID);
        g_W1s[(size_t)r * KF + k] = hhi(W1[(size_t)r * HID + k]);
    }
}

__global__ void prep_data(const float* __restrict__ ctx,
                          const float* __restrict__ last_pos,
                          const float* __restrict__ last_delta) {
    const long n_cs = (long)BATCH * CTXK;
    long i = (long)blockIdx.x * blockDim.x + threadIdx.x;
    if (i < n_cs) {
        int b = (int)(i / CTXK), k = (int)(i % CTXK);
        float v = ctx[i];
        g_ctxs[(size_t)b * ACLD + k]       = hhi(v);
        g_ctxs[(size_t)b * ACLD + 512 + k] = hlo(v);
        return;
    }
    i -= n_cs;
    if (i < BATCH) {
        int b = (int)i;
        g_pos[b * 2 + 0] = last_pos[b * 2 + 0];
        g_pos[b * 2 + 1] = last_pos[b * 2 + 1];
        float d0 = last_delta[b * 2 + 0], d1 = last_delta[b * 2 + 1];
        float nn = fmaxf(sqrtf(d0 * d0 + d1 * d1), 1e-6f);
        g_e[b * 4 + 0] = d0;
        g_e[b * 4 + 1] = d1;
        g_e[b * 4 + 2] = d0 / nn;
        g_e[b * 4 + 3] = d1 / nn;
    }
}

// ------------------------- GEMM engine (R6/R8-proven 128x128) -------------------------
// 128x128 CTA tile, KTILE=64, 3-slot ring / 2 tiles in flight, ldmatrix,
// one __syncthreads per K-tile. 256 threads, warp grid 2Mx4N, warp tile 64x32.
#define TK 64
#define NSTG 3
#define STG_BYTES 32768          // A 16KB + B 16KB
#define GEMM_SMEM (NSTG * STG_BYTES)

enum { EPI_CTX = 0, EPI_TANH_SPLIT = 1, EPI_TANH_C = 2, EPI_GATES = 3, EPI_GELU = 4 };

__device__ __forceinline__ void lstm_cell(float* cbuf, __half* outs, int row, int j,
                                          float gi, float gf, float gg, float go) {
    float cold = cbuf[(size_t)row * HID + j];
    float si = fsig(gi);
    float sf = fsig(gf);
    float so = fsig(go);
    float tg = ftanh(gg);
    float cn = sf * cold + si * tg;
    float h  = so * ftanh(cn);
    cbuf[(size_t)row * HID + j] = cn;
    outs[(size_t)row * AGLD + j] = hhi(h);
}

template <int EPI>
__global__ void __launch_bounds__(256, 2)
gemm2(const __half* __restrict__ A, int lda,
      const __half* __restrict__ W, int ktot,
      int s1, int d1,                        // K->A col mapping (per 64-tile)
      const float* __restrict__ aux,
      float* __restrict__ outf,
      __half* __restrict__ outs,
      int nOut) {
    extern __shared__ __align__(1024) char smp[];
    const uint32_t sbase = (uint32_t)__cvta_generic_to_shared(smp);

    const int tid = threadIdx.x;
    const int lane = tid & 31, wid = tid >> 5;
    const int wm = wid >> 2, wn = wid & 3;
    const int m0 = blockIdx.y * 128, n0 = blockIdx.x * 128;
    const int nK = ktot / TK;

    float acc[4][4][4];
#pragma unroll
    for (int a = 0; a < 4; a++)
#pragma unroll
        for (int b = 0; b < 4; b++)
#pragma unroll
            for (int c = 0; c < 4; c++) acc[a][b][c] = 0.f;

    auto fill = [&](int kt) {
        int slot = kt % NSTG;
        uint32_t sA = sbase + slot * STG_BYTES;
        uint32_t sB = sA + 16384;
        int k0 = kt * TK;
        int cb = (k0 < s1) ? k0 : k0 - d1;
#pragma unroll
        for (int t = 0; t < 4; t++) {
            int c = tid + t * 256;
            int row = c >> 3, ch = c & 7;
            cpasync16(sA + SW128(row * 128 + ch * 16),
                      A + (size_t)(m0 + row) * lda + cb + ch * 8);
        }
#pragma unroll
        for (int t = 0; t < 4; t++) {
            int c = tid + t * 256;
            int row = c >> 3, ch = c & 7;
            cpasync16(sB + SW128(row * 128 + ch * 16),
                      W + (size_t)(n0 + row) * ktot + k0 + ch * 8);
        }
        asm volatile("cp.async.commit_group;\n");
    };

    // prologue: 2 tiles in flight
    fill(0);
    if (nK > 1) fill(1);

    const int g  = lane >> 3;
    const int lr = lane & 7;

    for (int kt = 0; kt < nK; kt++) {
        if (kt + 1 < nK) asm volatile("cp.async.wait_group 1;\n");
        else             asm volatile("cp.async.wait_group 0;\n");
        __syncthreads();                       // all warps done reading slot (kt-1)%3
        if (kt + 2 < nK) fill(kt + 2);         // safe: overwrites slot (kt-1)%3

        int slot = kt % NSTG;
        uint32_t sA = sbase + slot * STG_BYTES;
        uint32_t sB = sA + 16384;

#pragma unroll
        for (int ks = 0; ks < 4; ks++) {
            uint32_t a[4][4], b[2][4];
#pragma unroll
            for (int mf = 0; mf < 4; mf++) {
                int row = wm * 64 + mf * 16 + lr + ((g & 1) << 3);
                ldsm4(a[mf], sA + SW128(row * 128 + ks * 32 + ((g >> 1) << 4)));
            }
#pragma unroll
            for (int nf = 0; nf < 2; nf++) {
                int row = wn * 32 + nf * 16 + lr + ((g >> 1) << 3);
                ldsm4(b[nf], sB + SW128(row * 128 + ks * 32 + ((g & 1) << 4)));
            }
#pragma unroll
            for (int mf = 0; mf < 4; mf++) {
#pragma unroll
                for (int nf = 0; nf < 2; nf++) {
                    mma16816(acc[mf][2 * nf],     a[mf], &b[nf][0]);
                    mma16816(acc[mf][2 * nf + 1], a[mf], &b[nf][2]);
                }
            }
        }
    }

    // ------------------------- epilogue -------------------------
#pragma unroll
    for (int mt = 0; mt < 4; mt++) {
#pragma unroll
        for (int nt = 0; nt < 4; nt++) {
            int r = m0 + wm * 64 + mt * 16 + (lane >> 2);
            int n = n0 + wn * 32 + nt * 8 + (lane & 3) * 2;
            float v0 = acc[mt][nt][0], v1 = acc[mt][nt][1];
            float v2 = acc[mt][nt][2], v3 = acc[mt][nt][3];

            if (EPI == EPI_CTX) {
                outf[(size_t)r * nOut + n]           = v0 + aux[n];
                outf[(size_t)r * nOut + n + 1]       = v1 + aux[n + 1];
                outf[(size_t)(r + 8) * nOut + n]     = v2 + aux[n];
                outf[(size_t)(r + 8) * nOut + n + 1] = v3 + aux[n + 1];
            } else if (EPI == EPI_TANH_C) {
                outf[(size_t)r * nOut + n]           = ftanh(v0 + aux[n]);
                outf[(size_t)r * nOut + n + 1]       = ftanh(v1 + aux[n + 1]);
                outf[(size_t)(r + 8) * nOut + n]     = ftanh(v2 + aux[n]);
                outf[(size_t)(r + 8) * nOut + n + 1] = ftanh(v3 + aux[n + 1]);
            } else if (EPI == EPI_TANH_SPLIT) {
#pragma unroll
                for (int q = 0; q < 4; q++) {
                    int rr = (q >= 2) ? r + 8 : r;
                    int nn = n + (q & 1);
                    float v = (q == 0) ? v0 : (q == 1) ? v1 : (q == 2) ? v2 : v3;
                    outs[(size_t)rr * AGLD + nn] = hhi(ftanh(v + aux[nn]));
                }
            } else if (EPI == EPI_GELU) {
#pragma unroll
                for (int q = 0; q < 4; q++) {
                    int rr = (q >= 2) ? r + 8 : r;
                    int nn = n + (q & 1);
                    float v = (q == 0) ? v0 : (q == 1) ? v1 : (q == 2) ? v2 : v3;
                    float u = v + aux[nn];
                    outf[(size_t)rr * nOut + nn] = 0.5f * u * (1.f + erff(u * 0.70710678118654752f));
                }
            } else { // EPI_GATES: add gctx + rank-4 extra term, then LSTM cell
                float4 e0 = *(const float4*)(g_e + (size_t)r * 4);
                float4 e1 = *(const float4*)(g_e + (size_t)(r + 8) * 4);
                float4 wa = *(const float4*)(g_We + (size_t)n * 4);
                float4 wb = *(const float4*)(g_We + (size_t)(n + 1) * 4);
                float xa0 = e0.x * wa.x + e0.y * wa.y + e0.z * wa.z + e0.w * wa.w;
                float xb0 = e0.x * wb.x + e0.y * wb.y + e0.z * wb.z + e0.w * wb.w;
                float xa1 = e1.x * wa.x + e1.y * wa.y + e1.z * wa.z + e1.w * wa.w;
                float xb1 = e1.x * wb.x + e1.y * wb.y + e1.z * wb.z + e1.w * wb.w;
                float w0 = v0 + aux[(size_t)r * N4 + n]           + xa0;
                float w1 = v1 + aux[(size_t)r * N4 + n + 1]       + xb0;
                float w2 = v2 + aux[(size_t)(r + 8) * N4 + n]     + xa1;
                float w3 = v3 + aux[(size_t)(r + 8) * N4 + n + 1] + xb1;
                float u0 = __shfl_xor_sync(0xffffffffu, w0, 1);
                float u1 = __shfl_xor_sync(0xffffffffu, w1, 1);
                float u2 = __shfl_xor_sync(0xffffffffu, w2, 1);
                float u3 = __shfl_xor_sync(0xffffffffu, w3, 1);
                if (!(lane & 1)) {   // even lanes own (i,f); lane^1 holds (g,o)
                    int j = n >> 2;
                    lstm_cell(outf, outs, r, j, w0, w1, u0, u1);
                    lstm_cell(outf, outs, r + 8, j, w2, w3, u2, u3);
                }
            }
        }
    }
}

// ------------------------- LayerNorm (warp per row) -------------------------
__global__ void ln_kernel(const __half* __restrict__ Ag,
                          const float* __restrict__ gam, const float* __restrict__ bet) {
    int warp = (blockIdx.x * blockDim.x + threadIdx.x) >> 5;
    int lane = threadIdx.x & 31;
    if (warp >= BATCH) return;
    size_t base = (size_t)warp * AGLD;
    float h[32];
    float s = 0.f, ss = 0.f;
#pragma unroll
    for (int i = 0; i < 32; i++) {
        int k = lane + 32 * i;
        float v = __half2float(Ag[base + k]);
        h[i] = v; s += v; ss += v * v;
    }
#pragma unroll
    for (int o = 16; o; o >>= 1) {
        s  += __shfl_xor_sync(0xffffffffu, s, o);
        ss += __shfl_xor_sync(0xffffffffu, ss, o);
    }
    float mu = s * (1.f / HID);
    float var = ss * (1.f / HID) - mu * mu;
    float inv = rsqrtf(var + 1e-5f);
    size_t ob = (size_t)warp * AFLD;
#pragma unroll
    for (int i = 0; i < 32; i++) {
        int k = lane + 32 * i;
        float y = (h[i] - mu) * inv * gam[k] + bet[k];
        g_Af[ob + k] = hhi(y);
    }
}

// ------------------------- delta / pos head (warp per row) -------------------------
__global__ void delta_kernel(const float* __restrict__ W2, const float* __restrict__ b2,
                             float* __restrict__ out, int t) {
    int warp = (blockIdx.x * blockDim.x + threadIdx.x) >> 5;
    int lane = threadIdx.x & 31;
    if (warp >= BATCH) return;
    const float* y = g_y2 + (size_t)warp * HID;
    float a0 = 0.f, a1 = 0.f;
#pragma unroll
    for (int i = 0; i < 32; i++) {
        int k = lane + 32 * i;
        float v = y[k];
        a0 += v * W2[k];
        a1 += v * W2[HID + k];
    }
#pragma unroll
    for (int o = 16; o; o >>= 1) {
        a0 += __shfl_xor_sync(0xffffffffu, a0, o);
        a1 += __shfl_xor_sync(0xffffffffu, a1, o);
    }
    if (lane == 0) {
        float d0 = a0 + b2[0], d1 = a1 + b2[1];
        float p0 = g_pos[warp * 2 + 0] + d0;
        float p1 = g_pos[warp * 2 + 1] + d1;
        g_pos[warp * 2 + 0] = p0;
        g_pos[warp * 2 + 1] = p1;
        out[(size_t)warp * (TSTEPS * 2) + t * 2 + 0] = p0;
        out[(size_t)warp * (TSTEPS * 2) + t * 2 + 1] = p1;
        float nn = fmaxf(sqrtf(d0 * d0 + d1 * d1), 1e-6f);
        g_e[warp * 4 + 0] = d0;
        g_e[warp * 4 + 1] = d1;
        g_e[warp * 4 + 2] = d0 / nn;
        g_e[warp * 4 + 3] = d1 / nn;
    }
}

// ------------------------- host -------------------------
static inline int nb(long n) { return (int)((n + 255) / 256); }

extern "C" void kernel_launch(void* const* d_in, const int* in_sizes, int n_in,
                              void* d_out, int out_size) {
    const float* context    = (const float*)d_in[0];
    const float* last_pos   = (const float*)d_in[1];
    const float* last_delta = (const float*)d_in[2];
    const float* Wh   = (const float*)d_in[3];
    const float* bh   = (const float*)d_in[4];
    const float* Wc   = (const float*)d_in[5];
    const float* bc   = (const float*)d_in[6];
    const float* W_ih = (const float*)d_in[7];
    const float* b_ih = (const float*)d_in[8];
    const float* W_hh = (const float*)d_in[9];
    const float* b_hh = (const float*)d_in[10];
    const float* ln_g = (const float*)d_in[11];
    const float* ln_b = (const float*)d_in[12];
    const float* W1   = (const float*)d_in[13];
    const float* b1   = (const float*)d_in[14];
    const float* W2   = (const float*)d_in[15];
    const float* b2   = (const float*)d_in[16];
    float* out = (float*)d_out;

    __half *pCtxs, *pAg0, *pAg1, *pAf, *pWg, *pWc4, *pWhh, *pWcc, *pW1s;
    float *pGctx, *pC, *pY2, *pBsum;
    cudaGetSymbolAddress((void**)&pCtxs, g_ctxs);
    cudaGetSymbolAddress((void**)&pAg0, g_Ag0);
    cudaGetSymbolAddress((void**)&pAg1, g_Ag1);
    cudaGetSymbolAddress((void**)&pAf,  g_Af);
    cudaGetSymbolAddress((void**)&pWg,  g_Wg);
    cudaGetSymbolAddress((void**)&pWc4, g_Wc4);
    cudaGetSymbolAddress((void**)&pWhh, g_Whh);
    cudaGetSymbolAddress((void**)&pWcc, g_Wcc);
    cudaGetSymbolAddress((void**)&pW1s, g_W1s);
    cudaGetSymbolAddress((void**)&pGctx, g_gctx);
    cudaGetSymbolAddress((void**)&pC,   g_c);
    cudaGetSymbolAddress((void**)&pY2,  g_y2);
    cudaGetSymbolAddress((void**)&pBsum, g_bsum);

    cudaFuncSetAttribute(gemm2<EPI_CTX>,        cudaFuncAttributeMaxDynamicSharedMemorySize, GEMM_SMEM);
    cudaFuncSetAttribute(gemm2<EPI_TANH_SPLIT>, cudaFuncAttributeMaxDynamicSharedMemorySize, GEMM_SMEM);
    cudaFuncSetAttribute(gemm2<EPI_TANH_C>,     cudaFuncAttributeMaxDynamicSharedMemorySize, GEMM_SMEM);
    cudaFuncSetAttribute(gemm2<EPI_GATES>,      cudaFuncAttributeMaxDynamicSharedMemorySize, GEMM_SMEM);
    cudaFuncSetAttribute(gemm2<EPI_GELU>,       cudaFuncAttributeMaxDynamicSharedMemorySize, GEMM_SMEM);

    const int BIG = 1 << 30;

    {
        long tot = (long)N4 * KG + (long)N4 * 4 + (long)N4 * KC + N4
                 + (long)HID * CTXK * 2 + (long)HID * HID;
        prep_weights<<<nb(tot), 256>>>(W_hh, W_ih, b_ih, b_hh, Wh, Wc, W1);
    }
    {
        long tot = (long)BATCH * CTXK + BATCH;
        prep_data<<<nb(tot), 256>>>(context, last_pos, last_delta);
    }

    dim3 blk(256);
    dim3 grid_n4(N4 / 128, BATCH / 128);   // (32,128)
    dim3 grid_h(HID / 128, BATCH / 128);   // (8,128)

    // gates_ctx (3-term), hidden/cell init (3-term)
    gemm2<EPI_CTX><<<grid_n4, blk, GEMM_SMEM>>>(pCtxs, ACLD, pWc4, KC, 1024, 1024,
                                                pBsum, pGctx, nullptr, N4);
    gemm2<EPI_TANH_SPLIT><<<grid_h, blk, GEMM_SMEM>>>(pCtxs, ACLD, pWhh, KC, 1024, 1024,
                                                      bh, nullptr, pAg0, HID);
    gemm2<EPI_TANH_C><<<grid_h, blk, GEMM_SMEM>>>(pCtxs, ACLD, pWcc, KC, 1024, 1024,
                                                  bc, pC, nullptr, HID);

    __half* Ag[2] = {pAg0, pAg1};
    for (int t = 0; t < TSTEPS; t++) {
        int cur = t & 1, nxt = cur ^ 1;
        gemm2<EPI_GATES><<<grid_n4, blk, GEMM_SMEM>>>(Ag[cur], AGLD, pWg, KG, BIG, 0,
                                                      pGctx, pC, Ag[nxt], N4);
        ln_kernel<<<BATCH / 8, 256>>>(Ag[nxt], ln_g, ln_b);
        gemm2<EPI_GELU><<<grid_h, blk, GEMM_SMEM>>>(pAf, AFLD, pW1s, KF, BIG, 0,
                                                    b1, pY2, nullptr, HID);
        delta_kernel<<<BATCH / 8, 256>>>(W2, b2, out, t);
    }
}

// round 15
// speedup vs baseline: 1.7523x; 1.0248x over previous
#include <cuda_runtime.h>
#include <cuda_fp16.h>
#include <math.h>
#include <stdint.h>

#define BATCH   16384
#define HID     1024
#define CTXK    512
#define N4      4096
#define TSTEPS  60
#define INW     516     // W_ih row width (C+4)

// gates GEMM (single-term fp16): A row = K row = [h_hi(1024)] -> KG=1024
// extra term e(4)x We(4,n) applied in the epilogue from g_e / g_We (fp32).
#define AGLD    1024
#define KG      1024
// ffn GEMM (single-term fp16): A row = K row = [y(1024)]; delta partials fused.
#define AFLD    1024
#define KF      1024
// context GEMMs (one-time, 3-term fp16): A row = [c_hi(512)|c_lo(512)];
//   K = [c_hi | c_lo | c_hi(re-read)] = 1536 ; W = [W_hi|W_hi|W_lo]
#define ACLD    1024
#define KC      1536
#define NPART   8            // FFN grid.x partials per row

// ------------------------- scratch (device globals) -------------------------
__device__ __align__(256) float   g_gctx[(size_t)BATCH * N4];
__device__ __align__(256) __half  g_Ag0[(size_t)BATCH * AGLD];
__device__ __align__(256) __half  g_Ag1[(size_t)BATCH * AGLD];
__device__ __align__(256) __half  g_Af [(size_t)BATCH * AFLD];
__device__ __align__(256) __half  g_ctxs[(size_t)BATCH * ACLD];
__device__ __align__(256) float   g_c  [(size_t)BATCH * HID];
__device__ __align__(256) float   g_py [(size_t)BATCH * NPART * 2];  // delta partials
__device__ __align__(256) float   g_pos[(size_t)BATCH * 2];
__device__ __align__(256) float   g_e  [(size_t)BATCH * 4];       // [pd0,pd1,hd0,hd1]
__device__ __align__(256) float   g_We [(size_t)N4 * 4];          // permuted W_extra
__device__ __align__(256) __half  g_Wg  [(size_t)N4 * KG];
__device__ __align__(256) __half  g_Wc4 [(size_t)N4 * KC];
__device__ __align__(256) __half  g_Whh [(size_t)HID * KC];
__device__ __align__(256) __half  g_Wcc [(size_t)HID * KC];
__device__ __align__(256) __half  g_W1s [(size_t)HID * KF];
__device__ __align__(256) float   g_bsum[N4];

// ------------------------- low-level helpers -------------------------
#define SW128(b) ((b) ^ (((b) >> 3) & 0x70))

__device__ __forceinline__ void cpasync16(uint32_t dst, const void* src) {
    asm volatile("cp.async.cg.shared.global [%0],[%1],16;\n" :: "r"(dst), "l"(src));
}
__device__ __forceinline__ void ldsm4(uint32_t* r, uint32_t addr) {
    asm volatile("ldmatrix.sync.aligned.m8n8.x4.shared.b16 {%0,%1,%2,%3}, [%4];"
                 : "=r"(r[0]), "=r"(r[1]), "=r"(r[2]), "=r"(r[3]) : "r"(addr));
}
__device__ __forceinline__ void mma16816(float* c, const uint32_t* a, const uint32_t* b) {
    asm volatile(
        "mma.sync.aligned.m16n8k16.row.col.f32.f16.f16.f32 "
        "{%0,%1,%2,%3},{%4,%5,%6,%7},{%8,%9},{%0,%1,%2,%3};\n"
        : "+f"(c[0]), "+f"(c[1]), "+f"(c[2]), "+f"(c[3])
        : "r"(a[0]), "r"(a[1]), "r"(a[2]), "r"(a[3]), "r"(b[0]), "r"(b[1]));
}
__device__ __forceinline__ __half hhi(float v) { return __float2half_rn(v); }
__device__ __forceinline__ __half hlo(float v) {
    return __float2half_rn(v - __half2float(__float2half_rn(v)));
}
// fast activations: __expf (MUFU.EX2) + __fdividef (MUFU.RCP), rel err ~2^-21
__device__ __forceinline__ float fsig(float x) {
    return __fdividef(1.f, 1.f + __expf(-x));
}
__device__ __forceinline__ float ftanh(float x) {
    return 1.f - __fdividef(2.f, __expf(2.f * x) + 1.f);   // exact identity
}

// ------------------------- prep kernels -------------------------
__global__ void prep_weights(const float* __restrict__ Whh, const float* __restrict__ Wih,
                             const float* __restrict__ b_ih, const float* __restrict__ b_hh,
                             const float* __restrict__ Wh, const float* __restrict__ Wc,
                             const float* __restrict__ W1) {
    const long n_wg = (long)N4 * KG;
    const long n_wc = (long)N4 * KC;
    const long n_s  = (long)HID * CTXK;
    const long n_w1 = (long)HID * HID;
    long i = (long)blockIdx.x * blockDim.x + threadIdx.x;

    if (i < n_wg) {   // single-term: Whh_hi, rows permuted n'=4j+g
        int np = (int)(i / KG), k = (int)(i % KG);
        int r = (np & 3) * HID + (np >> 2);
        g_Wg[(size_t)np * KG + k] = hhi(Whh[(size_t)r * HID + k]);
        return;
    }
    i -= n_wg;
    if (i < N4 * 4) { // W_extra permuted fp32 table [np][4]
        int np = (int)(i >> 2), q = (int)(i & 3);
        int r = (np & 3) * HID + (np >> 2);
        g_We[(size_t)np * 4 + q] = Wih[(size_t)r * INW + CTXK + q];
        return;
    }
    i -= N4 * 4;
    if (i < n_wc) {   // W_ih ctx part (3-term): [hi(512)|hi(512)|lo(512)]
        int np = (int)(i / KC), k = (int)(i % KC);
        int r = (np & 3) * HID + (np >> 2);
        int src = (k < 512) ? k : (k < 1024 ? k - 512 : k - 1024);
        float w = Wih[(size_t)r * INW + src];
        g_Wc4[(size_t)np * KC + k] = (k < 1024) ? hhi(w) : hlo(w);
        return;
    }
    i -= n_wc;
    if (i < N4) {
        int r = ((int)i & 3) * HID + ((int)i >> 2);
        g_bsum[i] = b_ih[r] + b_hh[r];
        return;
    }
    i -= N4;
    if (i < n_s) {    // Wh (3-term): [hi|hi|lo]
        int r = (int)(i / CTXK), k = (int)(i % CTXK);
        float w = Wh[(size_t)r * CTXK + k];
        size_t b = (size_t)r * KC;
        g_Whh[b + k] = hhi(w); g_Whh[b + 512 + k] = hhi(w); g_Whh[b + 1024 + k] = hlo(w);
        return;
    }
    i -= n_s;
    if (i < n_s) {    // Wc (3-term)
        int r = (int)(i / CTXK), k = (int)(i % CTXK);
        float w = Wc[(size_t)r * CTXK + k];
        size_t b = (size_t)r * KC;
        g_Wcc[b + k] = hhi(w); g_Wcc[b + 512 + k] = hhi(w); g_Wcc[b + 1024 + k] = hlo(w);
        return;
    }
    i -= n_s;
    if (i < n_w1) {   // W1 (single-term fp16)
        int r = (int)(i / HID), k = (int)(i % HID);
        g_W1s[(size_t)r * KF + k] = hhi(W1[(size_t)r * HID + k]);
    }
}

__global__ void prep_data(const float* __restrict__ ctx,
                          const float* __restrict__ last_pos,
                          const float* __restrict__ last_delta) {
    const long n_cs = (long)BATCH * CTXK;
    long i = (long)blockIdx.x * blockDim.x + threadIdx.x;
    if (i < n_cs) {
        int b = (int)(i / CTXK), k = (int)(i % CTXK);
        float v = ctx[i];
        g_ctxs[(size_t)b * ACLD + k]       = hhi(v);
        g_ctxs[(size_t)b * ACLD + 512 + k] = hlo(v);
        return;
    }
    i -= n_cs;
    if (i < BATCH) {
        int b = (int)i;
        g_pos[b * 2 + 0] = last_pos[b * 2 + 0];
        g_pos[b * 2 + 1] = last_pos[b * 2 + 1];
        float d0 = last_delta[b * 2 + 0], d1 = last_delta[b * 2 + 1];
        float nn = fmaxf(sqrtf(d0 * d0 + d1 * d1), 1e-6f);
        g_e[b * 4 + 0] = d0;
        g_e[b * 4 + 1] = d1;
        g_e[b * 4 + 2] = d0 / nn;
        g_e[b * 4 + 3] = d1 / nn;
    }
}

// ------------------------- GEMM engine (R6/R8-proven 128x128) -------------------------
// 128x128 CTA tile, KTILE=64, 3-slot ring / 2 tiles in flight, ldmatrix,
// one __syncthreads per K-tile. 256 threads, warp grid 2Mx4N, warp tile 64x32.
#define TK 64
#define NSTG 3
#define STG_BYTES 32768          // A 16KB + B 16KB
#define GEMM_SMEM (NSTG * STG_BYTES)

enum { EPI_CTX = 0, EPI_TANH_SPLIT = 1, EPI_TANH_C = 2, EPI_GATES = 3, EPI_GELU = 4 };

__device__ __forceinline__ void lstm_cell(float* cbuf, __half* outs, int row, int j,
                                          float gi, float gf, float gg, float go) {
    float cold = cbuf[(size_t)row * HID + j];
    float si = fsig(gi);
    float sf = fsig(gf);
    float so = fsig(go);
    float tg = ftanh(gg);
    float cn = sf * cold + si * tg;
    float h  = so * ftanh(cn);
    cbuf[(size_t)row * HID + j] = cn;
    outs[(size_t)row * AGLD + j] = hhi(h);
}

template <int EPI>
__global__ void __launch_bounds__(256, 2)
gemm2(const __half* __restrict__ A, int lda,
      const __half* __restrict__ W, int ktot,
      int s1, int d1,                        // K->A col mapping (per 64-tile)
      const float* __restrict__ aux,
      const float* __restrict__ aux2,        // W2 (EPI_GELU only)
      float* __restrict__ outf,
      __half* __restrict__ outs,
      int nOut) {
    extern __shared__ __align__(1024) char smp[];
    const uint32_t sbase = (uint32_t)__cvta_generic_to_shared(smp);

    const int tid = threadIdx.x;
    const int lane = tid & 31, wid = tid >> 5;
    const int wm = wid >> 2, wn = wid & 3;
    const int m0 = blockIdx.y * 128, n0 = blockIdx.x * 128;
    const int nK = ktot / TK;

    float acc[4][4][4];
#pragma unroll
    for (int a = 0; a < 4; a++)
#pragma unroll
        for (int b = 0; b < 4; b++)
#pragma unroll
            for (int c = 0; c < 4; c++) acc[a][b][c] = 0.f;

    auto fill = [&](int kt) {
        int slot = kt % NSTG;
        uint32_t sA = sbase + slot * STG_BYTES;
        uint32_t sB = sA + 16384;
        int k0 = kt * TK;
        int cb = (k0 < s1) ? k0 : k0 - d1;
#pragma unroll
        for (int t = 0; t < 4; t++) {
            int c = tid + t * 256;
            int row = c >> 3, ch = c & 7;
            cpasync16(sA + SW128(row * 128 + ch * 16),
                      A + (size_t)(m0 + row) * lda + cb + ch * 8);
        }
#pragma unroll
        for (int t = 0; t < 4; t++) {
            int c = tid + t * 256;
            int row = c >> 3, ch = c & 7;
            cpasync16(sB + SW128(row * 128 + ch * 16),
                      W + (size_t)(n0 + row) * ktot + k0 + ch * 8);
        }
        asm volatile("cp.async.commit_group;\n");
    };

    // prologue: 2 tiles in flight
    fill(0);
    if (nK > 1) fill(1);

    const int g  = lane >> 3;
    const int lr = lane & 7;

    for (int kt = 0; kt < nK; kt++) {
        if (kt + 1 < nK) asm volatile("cp.async.wait_group 1;\n");
        else             asm volatile("cp.async.wait_group 0;\n");
        __syncthreads();                       // all warps done reading slot (kt-1)%3
        if (kt + 2 < nK) fill(kt + 2);         // safe: overwrites slot (kt-1)%3

        int slot = kt % NSTG;
        uint32_t sA = sbase + slot * STG_BYTES;
        uint32_t sB = sA + 16384;

#pragma unroll
        for (int ks = 0; ks < 4; ks++) {
            uint32_t a[4][4], b[2][4];
#pragma unroll
            for (int mf = 0; mf < 4; mf++) {
                int row = wm * 64 + mf * 16 + lr + ((g & 1) << 3);
                ldsm4(a[mf], sA + SW128(row * 128 + ks * 32 + ((g >> 1) << 4)));
            }
#pragma unroll
            for (int nf = 0; nf < 2; nf++) {
                int row = wn * 32 + nf * 16 + lr + ((g >> 1) << 3);
                ldsm4(b[nf], sB + SW128(row * 128 + ks * 32 + ((g & 1) << 4)));
            }
#pragma unroll
            for (int mf = 0; mf < 4; mf++) {
#pragma unroll
                for (int nf = 0; nf < 2; nf++) {
                    mma16816(acc[mf][2 * nf],     a[mf], &b[nf][0]);
                    mma16816(acc[mf][2 * nf + 1], a[mf], &b[nf][2]);
                }
            }
        }
    }

    // ------------------------- epilogue -------------------------
    if (EPI == EPI_GELU) {
        // GELU + fused delta partials: p[row] = sum_n gelu(v+b1[n]) * W2[{0,1}][n]
        float pr0[8], pr1[8];
#pragma unroll
        for (int s = 0; s < 8; s++) { pr0[s] = 0.f; pr1[s] = 0.f; }
#pragma unroll
        for (int mt = 0; mt < 4; mt++) {
#pragma unroll
            for (int nt = 0; nt < 4; nt++) {
                int n = n0 + wn * 32 + nt * 8 + (lane & 3) * 2;
#pragma unroll
                for (int q = 0; q < 4; q++) {
                    int nn = n + (q & 1);
                    float v = acc[mt][nt][q];
                    float u = v + aux[nn];
                    float y = 0.5f * u * (1.f + erff(u * 0.70710678118654752f));
                    int s = mt * 2 + (q >> 1);
                    pr0[s] += y * aux2[nn];
                    pr1[s] += y * aux2[HID + nn];
                }
            }
        }
        // reduce across the 4 lanes sharing a row (lane&3)
#pragma unroll
        for (int s = 0; s < 8; s++) {
            float p0 = pr0[s], p1 = pr1[s];
            p0 += __shfl_xor_sync(0xffffffffu, p0, 1);
            p0 += __shfl_xor_sync(0xffffffffu, p0, 2);
            p1 += __shfl_xor_sync(0xffffffffu, p1, 1);
            p1 += __shfl_xor_sync(0xffffffffu, p1, 2);
            pr0[s] = p0; pr1[s] = p1;
        }
        __syncthreads();                      // mainloop smem reads done in ALL warps
        float* sred = (float*)smp;            // [128 rows][4 wn][2]
        if ((lane & 3) == 0) {
#pragma unroll
            for (int s = 0; s < 8; s++) {
                int rowl = wm * 64 + (s >> 1) * 16 + (lane >> 2) + (s & 1) * 8;
                sred[(rowl * 4 + wn) * 2 + 0] = pr0[s];
                sred[(rowl * 4 + wn) * 2 + 1] = pr1[s];
            }
        }
        __syncthreads();
        if (tid < 128) {
            float s0 = 0.f, s1 = 0.f;
#pragma unroll
            for (int w = 0; w < 4; w++) {     // fixed order: deterministic
                s0 += sred[(tid * 4 + w) * 2 + 0];
                s1 += sred[(tid * 4 + w) * 2 + 1];
            }
            ((float2*)outf)[(size_t)(m0 + tid) * NPART + blockIdx.x] = make_float2(s0, s1);
        }
        return;
    }

#pragma unroll
    for (int mt = 0; mt < 4; mt++) {
#pragma unroll
        for (int nt = 0; nt < 4; nt++) {
            int r = m0 + wm * 64 + mt * 16 + (lane >> 2);
            int n = n0 + wn * 32 + nt * 8 + (lane & 3) * 2;
            float v0 = acc[mt][nt][0], v1 = acc[mt][nt][1];
            float v2 = acc[mt][nt][2], v3 = acc[mt][nt][3];

            if (EPI == EPI_CTX) {
                outf[(size_t)r * nOut + n]           = v0 + aux[n];
                outf[(size_t)r * nOut + n + 1]       = v1 + aux[n + 1];
                outf[(size_t)(r + 8) * nOut + n]     = v2 + aux[n];
                outf[(size_t)(r + 8) * nOut + n + 1] = v3 + aux[n + 1];
            } else if (EPI == EPI_TANH_C) {
                outf[(size_t)r * nOut + n]           = ftanh(v0 + aux[n]);
                outf[(size_t)r * nOut + n + 1]       = ftanh(v1 + aux[n + 1]);
                outf[(size_t)(r + 8) * nOut + n]     = ftanh(v2 + aux[n]);
                outf[(size_t)(r + 8) * nOut + n + 1] = ftanh(v3 + aux[n + 1]);
            } else if (EPI == EPI_TANH_SPLIT) {
#pragma unroll
                for (int q = 0; q < 4; q++) {
                    int rr = (q >= 2) ? r + 8 : r;
                    int nn = n + (q & 1);
                    float v = (q == 0) ? v0 : (q == 1) ? v1 : (q == 2) ? v2 : v3;
                    outs[(size_t)rr * AGLD + nn] = hhi(ftanh(v + aux[nn]));
                }
            } else { // EPI_GATES: add gctx + rank-4 extra term, then LSTM cell
                float4 e0 = *(const float4*)(g_e + (size_t)r * 4);
                float4 e1 = *(const float4*)(g_e + (size_t)(r + 8) * 4);
                float4 wa = *(const float4*)(g_We + (size_t)n * 4);
                float4 wb = *(const float4*)(g_We + (size_t)(n + 1) * 4);
                float xa0 = e0.x * wa.x + e0.y * wa.y + e0.z * wa.z + e0.w * wa.w;
                float xb0 = e0.x * wb.x + e0.y * wb.y + e0.z * wb.z + e0.w * wb.w;
                float xa1 = e1.x * wa.x + e1.y * wa.y + e1.z * wa.z + e1.w * wa.w;
                float xb1 = e1.x * wb.x + e1.y * wb.y + e1.z * wb.z + e1.w * wb.w;
                float w0 = v0 + aux[(size_t)r * N4 + n]           + xa0;
                float w1 = v1 + aux[(size_t)r * N4 + n + 1]       + xb0;
                float w2 = v2 + aux[(size_t)(r + 8) * N4 + n]     + xa1;
                float w3 = v3 + aux[(size_t)(r + 8) * N4 + n + 1] + xb1;
                float u0 = __shfl_xor_sync(0xffffffffu, w0, 1);
                float u1 = __shfl_xor_sync(0xffffffffu, w1, 1);
                float u2 = __shfl_xor_sync(0xffffffffu, w2, 1);
                float u3 = __shfl_xor_sync(0xffffffffu, w3, 1);
                if (!(lane & 1)) {   // even lanes own (i,f); lane^1 holds (g,o)
                    int j = n >> 2;
                    lstm_cell(outf, outs, r, j, w0, w1, u0, u1);
                    lstm_cell(outf, outs, r + 8, j, w2, w3, u2, u3);
                }
            }
        }
    }
}

// ------------------------- LayerNorm (warp per row) -------------------------
__global__ void ln_kernel(const __half* __restrict__ Ag,
                          const float* __restrict__ gam, const float* __restrict__ bet) {
    int warp = (blockIdx.x * blockDim.x + threadIdx.x) >> 5;
    int lane = threadIdx.x & 31;
    if (warp >= BATCH) return;
    size_t base = (size_t)warp * AGLD;
    float h[32];
    float s = 0.f, ss = 0.f;
#pragma unroll
    for (int i = 0; i < 32; i++) {
        int k = lane + 32 * i;
        float v = __half2float(Ag[base + k]);
        h[i] = v; s += v; ss += v * v;
    }
#pragma unroll
    for (int o = 16; o; o >>= 1) {
        s  += __shfl_xor_sync(0xffffffffu, s, o);
        ss += __shfl_xor_sync(0xffffffffu, ss, o);
    }
    float mu = s * (1.f / HID);
    float var = ss * (1.f / HID) - mu * mu;
    float inv = rsqrtf(var + 1e-5f);
    size_t ob = (size_t)warp * AFLD;
#pragma unroll
    for (int i = 0; i < 32; i++) {
        int k = lane + 32 * i;
        float y = (h[i] - mu) * inv * gam[k] + bet[k];
        g_Af[ob + k] = hhi(y);
    }
}

// ------------------------- delta / pos head (thread per row) -------------------------
__global__ void delta_kernel(const float* __restrict__ b2,
                             float* __restrict__ out, int t) {
    int row = blockIdx.x * blockDim.x + threadIdx.x;
    if (row >= BATCH) return;
    const float2* pp = (const float2*)g_py + (size_t)row * NPART;
    float a0 = 0.f, a1 = 0.f;
#pragma unroll
    for (int i = 0; i < NPART; i++) {    // fixed order: deterministic
        float2 v = pp[i];
        a0 += v.x; a1 += v.y;
    }
    float d0 = a0 + b2[0], d1 = a1 + b2[1];
    float p0 = g_pos[row * 2 + 0] + d0;
    float p1 = g_pos[row * 2 + 1] + d1;
    g_pos[row * 2 + 0] = p0;
    g_pos[row * 2 + 1] = p1;
    out[(size_t)row * (TSTEPS * 2) + t * 2 + 0] = p0;
    out[(size_t)row * (TSTEPS * 2) + t * 2 + 1] = p1;
    float nn = fmaxf(sqrtf(d0 * d0 + d1 * d1), 1e-6f);
    g_e[row * 4 + 0] = d0;
    g_e[row * 4 + 1] = d1;
    g_e[row * 4 + 2] = d0 / nn;
    g_e[row * 4 + 3] = d1 / nn;
}

// ------------------------- host -------------------------
static inline int nb(long n) { return (int)((n + 255) / 256); }

extern "C" void kernel_launch(void* const* d_in, const int* in_sizes, int n_in,
                              void* d_out, int out_size) {
    const float* context    = (const float*)d_in[0];
    const float* last_pos   = (const float*)d_in[1];
    const float* last_delta = (const float*)d_in[2];
    const float* Wh   = (const float*)d_in[3];
    const float* bh   = (const float*)d_in[4];
    const float* Wc   = (const float*)d_in[5];
    const float* bc   = (const float*)d_in[6];
    const float* W_ih = (const float*)d_in[7];
    const float* b_ih = (const float*)d_in[8];
    const float* W_hh = (const float*)d_in[9];
    const float* b_hh = (const float*)d_in[10];
    const float* ln_g = (const float*)d_in[11];
    const float* ln_b = (const float*)d_in[12];
    const float* W1   = (const float*)d_in[13];
    const float* b1   = (const float*)d_in[14];
    const float* W2   = (const float*)d_in[15];
    const float* b2   = (const float*)d_in[16];
    float* out = (float*)d_out;

    __half *pCtxs, *pAg0, *pAg1, *pAf, *pWg, *pWc4, *pWhh, *pWcc, *pW1s;
    float *pGctx, *pC, *pPy, *pBsum;
    cudaGetSymbolAddress((void**)&pCtxs, g_ctxs);
    cudaGetSymbolAddress((void**)&pAg0, g_Ag0);
    cudaGetSymbolAddress((void**)&pAg1, g_Ag1);
    cudaGetSymbolAddress((void**)&pAf,  g_Af);
    cudaGetSymbolAddress((void**)&pWg,  g_Wg);
    cudaGetSymbolAddress((void**)&pWc4, g_Wc4);
    cudaGetSymbolAddress((void**)&pWhh, g_Whh);
    cudaGetSymbolAddress((void**)&pWcc, g_Wcc);
    cudaGetSymbolAddress((void**)&pW1s, g_W1s);
    cudaGetSymbolAddress((void**)&pGctx, g_gctx);
    cudaGetSymbolAddress((void**)&pC,   g_c);
    cudaGetSymbolAddress((void**)&pPy,  g_py);
    cudaGetSymbolAddress((void**)&pBsum, g_bsum);

    cudaFuncSetAttribute(gemm2<EPI_CTX>,        cudaFuncAttributeMaxDynamicSharedMemorySize, GEMM_SMEM);
    cudaFuncSetAttribute(gemm2<EPI_TANH_SPLIT>, cudaFuncAttributeMaxDynamicSharedMemorySize, GEMM_SMEM);
    cudaFuncSetAttribute(gemm2<EPI_TANH_C>,     cudaFuncAttributeMaxDynamicSharedMemorySize, GEMM_SMEM);
    cudaFuncSetAttribute(gemm2<EPI_GATES>,      cudaFuncAttributeMaxDynamicSharedMemorySize, GEMM_SMEM);
    cudaFuncSetAttribute(gemm2<EPI_GELU>,       cudaFuncAttributeMaxDynamicSharedMemorySize, GEMM_SMEM);

    const int BIG = 1 << 30;

    {
        long tot = (long)N4 * KG + (long)N4 * 4 + (long)N4 * KC + N4
                 + (long)HID * CTXK * 2 + (long)HID * HID;
        prep_weights<<<nb(tot), 256>>>(W_hh, W_ih, b_ih, b_hh, Wh, Wc, W1);
    }
    {
        long tot = (long)BATCH * CTXK + BATCH;
        prep_data<<<nb(tot), 256>>>(context, last_pos, last_delta);
    }

    dim3 blk(256);
    dim3 grid_n4(N4 / 128, BATCH / 128);   // (32,128)
    dim3 grid_h(HID / 128, BATCH / 128);   // (8,128)

    // gates_ctx (3-term), hidden/cell init (3-term)
    gemm2<EPI_CTX><<<grid_n4, blk, GEMM_SMEM>>>(pCtxs, ACLD, pWc4, KC, 1024, 1024,
                                                pBsum, nullptr, pGctx, nullptr, N4);
    gemm2<EPI_TANH_SPLIT><<<grid_h, blk, GEMM_SMEM>>>(pCtxs, ACLD, pWhh, KC, 1024, 1024,
                                                      bh, nullptr, nullptr, pAg0, HID);
    gemm2<EPI_TANH_C><<<grid_h, blk, GEMM_SMEM>>>(pCtxs, ACLD, pWcc, KC, 1024, 1024,
                                                  bc, nullptr, pC, nullptr, HID);

    __half* Ag[2] = {pAg0, pAg1};
    for (int t = 0; t < TSTEPS; t++) {
        int cur = t & 1, nxt = cur ^ 1;
        gemm2<EPI_GATES><<<grid_n4, blk, GEMM_SMEM>>>(Ag[cur], AGLD, pWg, KG, BIG, 0,
                                                      pGctx, nullptr, pC, Ag[nxt], N4);
        ln_kernel<<<BATCH / 8, 256>>>(Ag[nxt], ln_g, ln_b);
        gemm2<EPI_GELU><<<grid_h, blk, GEMM_SMEM>>>(pAf, AFLD, pW1s, KF, BIG, 0,
                                                    b1, W2, pPy, nullptr, HID);
        delta_kernel<<<nb(BATCH), 256>>>(b2, out, t);
    }
}